// round 15
// baseline (speedup 1.0000x reference)
#include <cuda_runtime.h>
#include <cuda_fp16.h>
#include <mma.h>
#include <math.h>
#include <stdint.h>

using namespace nvcuda;
typedef __half h16;

#define EPS 1e-5f
#define BATCH 4
#define HH 64
#define WW 64
#define HW 4096
#define BHW 16384
#define CC 512
#define KK 19
#define PP 64
#define NN 64
#define DD 256

__device__ float g_Fnhwc[BATCH * HW * CC];
__device__ float g_Fl[BATCH * PP * KK * CC];
__device__ float g_Fg[BATCH * KK * CC];
__device__ float g_query[BATCH * HW * DD];
__device__ float g_key[BATCH * PP * KK * DD];
__device__ float g_value[BATCH * KK * DD];
__device__ float g_x3[BATCH * HW * CC];

__device__ h16 g_F16[BATCH * HW * CC];
__device__ h16 g_h16[BATCH * PP * KK * CC];
__device__ h16 g_Fl216[BATCH * PP * KK * CC];
__device__ h16 g_Fs16[BATCH * HW * DD];
__device__ h16 g_Fo1b[32 * BHW * 16];
__device__ h16 g_catb[(size_t)160 * BHW * 16];

__device__ h16 g_w2b[4 * 32 * 19584];
__device__ h16 g_w3b[(size_t)4 * 160 * 19584];
__device__ h16 g_qw16[512 * 256];
__device__ h16 g_kw16[512 * 256];
__device__ h16 g_lgw16[512 * 512];
__device__ h16 g_c116[256 * 512];

__device__ __forceinline__ void cpa16(void* sdst, const void* gsrc) {
    unsigned int s = (unsigned int)__cvta_generic_to_shared(sdst);
    asm volatile("cp.async.cg.shared.global [%0], [%1], 16;" :: "r"(s), "l"(gsrc));
}
__device__ __forceinline__ void cpa16p(unsigned int sdst, const void* gsrc, bool pred) {
    int sz = pred ? 16 : 0;
    asm volatile("cp.async.cg.shared.global [%0], [%1], 16, %2;" :: "r"(sdst), "l"(gsrc), "r"(sz));
}
__device__ __forceinline__ void cpa_commit() { asm volatile("cp.async.commit_group;"); }
template <int N>
__device__ __forceinline__ void cpa_wait() { asm volatile("cp.async.wait_group %0;" :: "n"(N)); }

__device__ __forceinline__ void bulk_cp(unsigned int sdst, const void* gsrc,
                                        unsigned int bytes, unsigned int mbar) {
    asm volatile(
        "cp.async.bulk.shared::cta.global.mbarrier::complete_tx::bytes [%0], [%1], %2, [%3];"
        :: "r"(sdst), "l"(gsrc), "r"(bytes), "r"(mbar) : "memory");
}
__device__ __forceinline__ void mbar_init(unsigned int m, unsigned int c) {
    asm volatile("mbarrier.init.shared.b64 [%0], %1;" :: "r"(m), "r"(c) : "memory");
}
__device__ __forceinline__ void mbar_expect(unsigned int m, unsigned int tx) {
    asm volatile("mbarrier.arrive.expect_tx.shared.b64 _, [%0], %1;" :: "r"(m), "r"(tx) : "memory");
}
__device__ __forceinline__ void mbar_wait(unsigned int m, unsigned int par) {
    unsigned int done;
    asm volatile(
        "{\n\t.reg .pred p;\n\t"
        "mbarrier.try_wait.parity.acquire.cta.shared::cta.b64 p, [%1], %2;\n\t"
        "selp.b32 %0, 1, 0, p;\n\t}" : "=r"(done) : "r"(m), "r"(par) : "memory");
    if (!done) {
        asm volatile(
            "{\n\t.reg .pred P1;\n\tWL_%=:\n\t"
            "mbarrier.try_wait.parity.acquire.cta.shared::cta.b64 P1, [%0], %1, 0x989680;\n\t"
            "@P1 bra.uni WD_%=;\n\tbra.uni WL_%=;\n\tWD_%=:\n\t}"
            :: "r"(m), "r"(par) : "memory");
    }
}

// ---------------- transposes / preps ----------------
__global__ void k_transpose_f(const float* __restrict__ in, float* __restrict__ out,
                              h16* __restrict__ o16) {
    __shared__ float tile[32][33];
    int b = blockIdx.z, hw0 = blockIdx.x * 32, c0 = blockIdx.y * 32;
    int tx = threadIdx.x, ty = threadIdx.y;
    for (int i = ty; i < 32; i += 8)
        tile[i][tx] = in[((size_t)b * CC + c0 + i) * HW + hw0 + tx];
    __syncthreads();
    for (int i = ty; i < 32; i += 8) {
        float v = tile[tx][i];
        size_t o = ((size_t)b * HW + hw0 + i) * CC + c0 + tx;
        out[o] = v;
        o16[o] = __float2half(v);
    }
}
__global__ void k_transpose_m1(const float* __restrict__ in, h16* __restrict__ ob) {
    __shared__ float tile[32][33];
    int b = blockIdx.z, hw0 = blockIdx.x * 32, c0 = blockIdx.y * 32;
    int tx = threadIdx.x, ty = threadIdx.y;
    for (int i = ty; i < 32; i += 8)
        tile[i][tx] = in[((size_t)b * 2048 + c0 + i) * HW + hw0 + tx];
    __syncthreads();
    for (int i = ty; i < 32; i += 8) {
        int cg = 512 + c0 + tx;
        size_t o = ((size_t)(cg >> 4) * BHW + (size_t)b * HW + hw0 + i) * 16 + (cg & 15);
        ob[o] = __float2half(tile[tx][i]);
    }
}
__global__ void k_wprep(const float* __restrict__ w, h16* __restrict__ dst,
                        int Cin, int csteps) {
    size_t d = (size_t)blockIdx.x * 256 + threadIdx.x;
    size_t total = (size_t)4 * csteps * 19584;
    if (d >= total) return;
    int oc = d % 136;
    size_t r = d / 136;
    int k = r % 16; r /= 16;
    int tap = r % 9; r /= 9;
    int ch = r % csteps;
    int nt = r / csteps;
    h16 outv = __float2half(0.f);
    if (oc < 128)
        outv = __float2half(w[((size_t)(nt * 128 + oc) * Cin + ch * 16 + k) * 9 + tap]);
    dst[d] = outv;
}
__global__ void k_wt16x(const float* __restrict__ w0, h16* __restrict__ o0,
                        const float* __restrict__ w1, h16* __restrict__ o1,
                        const float* __restrict__ w2, h16* __restrict__ o2,
                        const float* __restrict__ w3, h16* __restrict__ o3) {
    int which = blockIdx.y;
    const float* w = which == 0 ? w0 : which == 1 ? w1 : which == 2 ? w2 : w3;
    h16* o = which == 0 ? o0 : which == 1 ? o1 : which == 2 ? o2 : o3;
    int K = which == 3 ? 256 : 512;
    int N = which == 2 ? 512 : which == 3 ? 512 : 256;
    int d = blockIdx.x * 256 + threadIdx.x;
    if (d >= K * N) return;
    int k = d / N, n = d % N;
    o[d] = __float2half(w[(size_t)n * K + k]);
}

// ---------------- patch softmax + F_l ----------------
__global__ void k_patch_fl(const float* __restrict__ I, const float* __restrict__ R) {
    int bp = blockIdx.x, b = bp >> 6, p = bp & 63;
    int ph = p >> 3, pw = p & 7, tid = threadIdx.x;
    __shared__ float lg[KK][NN];
    __shared__ float pix[NN][20];
    __shared__ float bc[KK];
    __shared__ float Fp[NN][65];
    for (int idx = tid; idx < KK * NN; idx += 256) {
        int k = idx / NN, n = idx % NN;
        int h = ph * 8 + (n >> 3), w = pw * 8 + (n & 7);
        lg[k][n] = I[(((size_t)b * KK + k) * HH + h) * WW + w];
    }
    if (tid < KK) bc[tid] = R[((size_t)b * KK + tid) * PP + p];
    __syncthreads();
    if (tid < KK) {
        float mx = -1e30f;
        for (int n = 0; n < NN; n++) mx = fmaxf(mx, lg[tid][n]);
        float s = 0.f;
        for (int n = 0; n < NN; n++) { float e = __expf(lg[tid][n] - mx); pix[n][tid] = e; s += e; }
        float inv = 1.f / s;
        for (int n = 0; n < NN; n++) pix[n][tid] *= inv;
    }
    __syncthreads();
    for (int c0 = 0; c0 < CC; c0 += 64) {
        for (int idx = tid; idx < NN * 64; idx += 256) {
            int n = idx >> 6, cc = idx & 63;
            int h = ph * 8 + (n >> 3), w = pw * 8 + (n & 7);
            Fp[n][cc] = g_Fnhwc[((size_t)b * HW + h * WW + w) * CC + c0 + cc];
        }
        __syncthreads();
        for (int o = tid; o < KK * 64; o += 256) {
            int k = o >> 6, cc = o & 63;
            float acc = 0.f;
            #pragma unroll 8
            for (int n = 0; n < NN; n++) acc += pix[n][k] * Fp[n][cc];
            g_Fl[((size_t)bp * KK + k) * CC + c0 + cc] = acc * bc[k];
        }
        __syncthreads();
    }
}

__global__ void k_lg1(const float* __restrict__ lg_w1) {
    int c0 = blockIdx.x * 64, bk = blockIdx.y;
    int b = bk / KK, k = bk % KK, tid = threadIdx.x;
    __shared__ float w1[64][64];
    __shared__ float Fl[64][65];
    for (int idx = tid; idx < 4096; idx += 256) w1[idx >> 6][idx & 63] = lg_w1[idx];
    for (int idx = tid; idx < 4096; idx += 256) {
        int p = idx >> 6, cc = idx & 63;
        Fl[p][cc] = g_Fl[(((size_t)b * PP + p) * KK + k) * CC + c0 + cc];
    }
    __syncthreads();
    for (int o = tid; o < 4096; o += 256) {
        int q = o >> 6, cc = o & 63;
        float acc = Fl[q][cc];
        #pragma unroll 8
        for (int p = 0; p < 64; p++) acc += w1[q][p] * Fl[p][cc];
        g_h16[(((size_t)b * PP + q) * KK + k) * CC + c0 + cc] = __float2half(fmaxf(acc, 0.f));
    }
}

__global__ void k_gemm_v(const float* __restrict__ A, const float* __restrict__ Bw,
                         float* __restrict__ C, int M, int N, int K,
                         const float* __restrict__ bias) {
    __shared__ float As[16][68];
    __shared__ float Bs[16][68];
    int m0 = blockIdx.y * 64, n0 = blockIdx.x * 64, tid = threadIdx.x;
    int tx = tid & 15, ty = tid >> 4;
    float acc[4][4] = {};
    for (int k0 = 0; k0 < K; k0 += 16) {
        for (int idx = tid; idx < 1024; idx += 256) {
            int i = idx >> 4, kk = idx & 15;
            int m = m0 + i;
            As[kk][i] = (m < M) ? A[(size_t)m * K + k0 + kk] : 0.f;
        }
        for (int idx = tid; idx < 1024; idx += 256) {
            int j = idx >> 4, kk = idx & 15;
            Bs[kk][j] = Bw[(size_t)(n0 + j) * K + k0 + kk];
        }
        __syncthreads();
        #pragma unroll
        for (int kk = 0; kk < 16; kk++) {
            float a[4], bv[4];
            #pragma unroll
            for (int i = 0; i < 4; i++) a[i] = As[kk][ty * 4 + i];
            #pragma unroll
            for (int j = 0; j < 4; j++) bv[j] = Bs[kk][tx * 4 + j];
            #pragma unroll
            for (int i = 0; i < 4; i++)
                #pragma unroll
                for (int j = 0; j < 4; j++) acc[i][j] += a[i] * bv[j];
        }
        __syncthreads();
    }
    #pragma unroll
    for (int i = 0; i < 4; i++) {
        int m = m0 + ty * 4 + i;
        if (m >= M) continue;
        #pragma unroll
        for (int j = 0; j < 4; j++)
            C[(size_t)m * N + n0 + tx * 4 + j] = acc[i][j] + bias[n0 + tx * 4 + j];
    }
}

__global__ void k_fuse(const float* __restrict__ fw, const float* __restrict__ fb) {
    int bk = blockIdx.x, c = threadIdx.x;
    int b = bk / KK, k = bk % KK;
    float acc = fb[0];
    #pragma unroll 8
    for (int p = 0; p < PP; p++)
        acc += fw[p] * __half2float(g_Fl216[(((size_t)b * PP + p) * KK + k) * CC + c]);
    g_Fg[(size_t)bk * CC + c] = acc;
}

__global__ void k_attn() {
    int bp = blockIdx.x, b = bp >> 6, p = bp & 63;
    int ph = p >> 3, pw = p & 7, tid = threadIdx.x;
    __shared__ float ks[KK][DD];
    __shared__ float vs[KK][DD];
    for (int idx = tid; idx < KK * DD; idx += 256)
        ((float*)ks)[idx] = g_key[(size_t)bp * KK * DD + idx];
    for (int idx = tid; idx < KK * DD; idx += 256)
        ((float*)vs)[idx] = g_value[(size_t)b * KK * DD + idx];
    __syncthreads();
    int warp = tid >> 5, lane = tid & 31;
    for (int n = warp; n < NN; n += 8) {
        int h = ph * 8 + (n >> 3), w = pw * 8 + (n & 7);
        const float* qrow = &g_query[((size_t)b * HW + h * WW + w) * DD];
        float qr[8];
        #pragma unroll
        for (int i = 0; i < 8; i++) qr[i] = qrow[i * 32 + lane];
        float acc[KK];
        #pragma unroll
        for (int k = 0; k < KK; k++) acc[k] = 0.f;
        #pragma unroll
        for (int i = 0; i < 8; i++) {
            float qd = qr[i];
            #pragma unroll
            for (int k = 0; k < KK; k++) acc[k] += qd * ks[k][i * 32 + lane];
        }
        #pragma unroll
        for (int k = 0; k < KK; k++)
            #pragma unroll
            for (int off = 16; off > 0; off >>= 1)
                acc[k] += __shfl_xor_sync(0xFFFFFFFFu, acc[k], off);
        float mx = -1e30f;
        #pragma unroll
        for (int k = 0; k < KK; k++) mx = fmaxf(mx, acc[k]);
        float sum = 0.f;
        #pragma unroll
        for (int k = 0; k < KK; k++) { acc[k] = __expf(acc[k] - mx); sum += acc[k]; }
        float inv = 1.f / sum;
        #pragma unroll
        for (int k = 0; k < KK; k++) acc[k] *= inv;
        size_t ob = ((size_t)b * HW + h * WW + w) * DD;
        #pragma unroll
        for (int i = 0; i < 8; i++) {
            int d = i * 32 + lane;
            float o = 0.f;
            #pragma unroll
            for (int k = 0; k < KK; k++) o += acc[k] * vs[k][d];
            g_Fs16[ob + d] = __float2half(o);
        }
    }
}

// ---------------- 1-term fp16 wmma GEMM (unchanged from R14) ----------------
#define GSTAGE_B 12544
template <int MODE>
__global__ __launch_bounds__(512)
void k_gemm_mma(const h16* __restrict__ Ag, const h16* __restrict__ Wt,
                int K, int N,
                float* __restrict__ Cf, h16* __restrict__ C16,
                const float* __restrict__ bias,
                const float* __restrict__ bng, const float* __restrict__ bnb,
                const float* __restrict__ resid) {
    extern __shared__ char smem[];
    int n0 = blockIdx.x * 128, m0 = blockIdx.y * 256;
    int tid = threadIdx.x, lane = tid & 31, warp = tid >> 5;
    int warpM = warp >> 1, warpN = warp & 1;
    int iters = K >> 4;

    wmma::fragment<wmma::accumulator, 16, 16, 16, float> acc[2][4];
    #pragma unroll
    for (int mt = 0; mt < 2; mt++)
        #pragma unroll
        for (int nj = 0; nj < 4; nj++) wmma::fill_fragment(acc[mt][nj], 0.f);

    auto issue = [&](int it) {
        int k0 = it << 4;
        char* base = smem + (it & 1) * GSTAGE_B;
        h16* As = (h16*)base;
        h16* Ws = (h16*)(base + 8192);
        {
            int flat = tid * 8;
            int r = flat >> 4, c8 = flat & 15;
            cpa16(As + flat, Ag + (size_t)(m0 + r) * K + k0 + c8);
        }
        if (tid < 256) {
            int flat = tid * 8;
            int kk = flat >> 7, n8 = flat & 127;
            cpa16(Ws + kk * 136 + n8, Wt + (size_t)(k0 + kk) * N + n0 + n8);
        }
        cpa_commit();
    };

    issue(0);
    for (int it = 0; it < iters; it++) {
        cpa_wait<0>();
        __syncthreads();
        if (it + 1 < iters) issue(it + 1);
        char* base = smem + (it & 1) * GSTAGE_B;
        h16* As = (h16*)base;
        h16* Ws = (h16*)(base + 8192);
        #pragma unroll
        for (int mt = 0; mt < 2; mt++) {
            int t = warpM * 2 + mt;
            wmma::fragment<wmma::matrix_a, 16, 16, 16, h16, wmma::row_major> af;
            wmma::load_matrix_sync(af, As + t * 256, 16);
            #pragma unroll
            for (int nj = 0; nj < 4; nj++) {
                wmma::fragment<wmma::matrix_b, 16, 16, 16, h16, wmma::row_major> bf;
                wmma::load_matrix_sync(bf, Ws + warpN * 64 + nj * 16, 136);
                wmma::mma_sync(acc[mt][nj], af, bf, acc[mt][nj]);
            }
        }
        __syncthreads();
    }

    float* buf = (float*)smem + warp * 320;
    #pragma unroll
    for (int mt = 0; mt < 2; mt++) {
        int t = warpM * 2 + mt;
        #pragma unroll
        for (int nj = 0; nj < 4; nj++) {
            wmma::store_matrix_sync(buf, acc[mt][nj], 20, wmma::mem_row_major);
            __syncwarp();
            #pragma unroll
            for (int l = 0; l < 8; l++) {
                int e = l * 32 + lane;
                int r = e >> 4, c = e & 15;
                int gm = m0 + t * 16 + r;
                int gn = n0 + warpN * 64 + nj * 16 + c;
                float v = buf[r * 20 + c];
                size_t o = (size_t)gm * N + gn;
                if (MODE == 0) {
                    C16[o] = __float2half(v);
                } else if (MODE == 1) {
                    Cf[o] = v + bias[gn];
                } else {
                    float s = bng[gn] * rsqrtf(1.f + EPS);
                    v = resid[o] + fmaxf(v * s + bnb[gn], 0.f);
                    C16[((size_t)(gn >> 4) * BHW + gm) * 16 + (gn & 15)] = __float2half(v);
                }
            }
            __syncwarp();
        }
    }
}

// ---------------- conv: padded-A (48B px stride, conflict-free), W bulk, 3-stage ----------------
// stage: A[6 rows][66 px][24 halfs]=19008B | W[9][16][136]=39168B = 58176B
#define SW_OFF 19008
#define CSTG 58176
#define CONVB_SMEM (3 * CSTG + 64)
__global__ __launch_bounds__(512, 1)
void k_conv_bulk(const h16* __restrict__ inb, int csteps, const h16* __restrict__ wb,
                 const float* __restrict__ bng, const float* __restrict__ bnb,
                 float* __restrict__ out_f, h16* __restrict__ ob) {
    extern __shared__ char dsm[];
    char* aptr = (char*)(((size_t)dsm + 127) & ~(size_t)127);
    unsigned int abase = (unsigned int)__cvta_generic_to_shared(aptr);
    unsigned int mbs = abase + 3 * CSTG;

    int tid = threadIdx.x, lane = tid & 31, warp = tid >> 5;
    int warpM = warp >> 1, warpN = warp & 1;
    int b = blockIdx.x >> 4, h0 = (blockIdx.x & 15) << 2;
    int nt = blockIdx.y;
    int oc0 = nt << 7;

    if (tid < 3) mbar_init(mbs + tid * 8, 1);
    __syncthreads();

    auto issue = [&](int s) {
        int bi = s % 3;
        unsigned int base = abase + bi * CSTG;
        if (tid == 0) {
            unsigned int mb = mbs + bi * 8;
            mbar_expect(mb, 39168u);
            bulk_cp(base + SW_OFF, wb + (size_t)(nt * csteps + s) * 19584, 39168, mb);
        }
        // A: 6 rows x 66 px x 16 ch -> padded px stride 48B; zfill halos
        for (int u = tid; u < 792; u += 512) {
            int inrow = u / 132;
            int rem = u - inrow * 132;
            int px = rem >> 1, half = rem & 1;
            int gh = h0 + inrow - 1, gpx = px - 1;
            bool pred = (gh >= 0 && gh < HH && gpx >= 0 && gpx < WW);
            const h16* g = pred
                ? inb + (((size_t)(s * BATCH + b) * HH + gh) * WW + gpx) * 16 + half * 8
                : inb;
            cpa16p(base + inrow * 3168 + px * 48 + half * 16, g, pred);
        }
        cpa_commit();
    };

    issue(0);
    if (csteps > 1) issue(1);
    if (csteps > 2) issue(2);
    int ph[3] = {0, 0, 0};

    wmma::fragment<wmma::accumulator, 16, 16, 16, float> acc[2][4];
    #pragma unroll
    for (int mt = 0; mt < 2; mt++)
        #pragma unroll
        for (int nj = 0; nj < 4; nj++) wmma::fill_fragment(acc[mt][nj], 0.f);

    for (int s = 0; s < csteps; s++) {
        int bi = s % 3;
        cpa_wait<2>();
        mbar_wait(mbs + bi * 8, ph[bi]); ph[bi] ^= 1;
        __syncthreads();
        char* base = aptr + bi * CSTG;
        h16* As = (h16*)base;
        h16* Ws = (h16*)(base + SW_OFF);

        #pragma unroll
        for (int tap = 0; tap < 9; tap++) {
            int ky = tap / 3, kx = tap % 3;
            wmma::fragment<wmma::matrix_a, 16, 16, 16, h16, wmma::row_major> af[2];
            #pragma unroll
            for (int mt = 0; mt < 2; mt++) {
                int t = warpM * 2 + mt;
                int row_l = t >> 2, px0 = (t & 3) * 16;
                wmma::load_matrix_sync(af[mt], As + ((row_l + ky) * 66 + px0 + kx) * 24, 24);
            }
            #pragma unroll
            for (int nj = 0; nj < 4; nj++) {
                wmma::fragment<wmma::matrix_b, 16, 16, 16, h16, wmma::row_major> bf;
                wmma::load_matrix_sync(bf, Ws + tap * 2176 + warpN * 64 + nj * 16, 136);
                #pragma unroll
                for (int mt = 0; mt < 2; mt++)
                    wmma::mma_sync(acc[mt][nj], af[mt], bf, acc[mt][nj]);
            }
        }
        __syncthreads();
        if (s + 3 < csteps) issue(s + 3);
    }

    float* buf = (float*)aptr + warp * 320;
    #pragma unroll
    for (int mt = 0; mt < 2; mt++) {
        int t = warpM * 2 + mt;
        int row_l = t >> 2, px0 = (t & 3) * 16;
        int grow = h0 + row_l;
        #pragma unroll
        for (int nj = 0; nj < 4; nj++) {
            wmma::store_matrix_sync(buf, acc[mt][nj], 20, wmma::mem_row_major);
            __syncwarp();
            #pragma unroll
            for (int l = 0; l < 8; l++) {
                int e = l * 32 + lane;
                int r = e >> 4, c = e & 15;
                int gn = oc0 + warpN * 64 + nj * 16 + c;
                int pix = (b * HH + grow) * WW + px0 + r;
                float v = buf[r * 20 + c];
                float sc = bng[gn] * rsqrtf(1.f + EPS);
                v = fmaxf(v * sc + bnb[gn], 0.f);
                if (out_f) out_f[(size_t)pix * CC + gn] = v;
                else ob[((size_t)(gn >> 4) * BHW + pix) * 16 + (gn & 15)] = __float2half(v);
            }
            __syncwarp();
        }
    }
}

// ---------------- classifier ----------------
__global__ void k_classifier(const float* __restrict__ drop_w, float* __restrict__ out) {
    __shared__ float Xs[32][65];
    __shared__ float Ws[KK][33];
    int tid = threadIdx.x;
    int row0 = blockIdx.x * 64;
    int b = row0 >> 12, hw0 = row0 & 4095;
    float acc[5] = {0.f, 0.f, 0.f, 0.f, 0.f};
    for (int c0 = 0; c0 < CC; c0 += 32) {
        for (int idx = tid; idx < 2048; idx += 256) {
            int r = idx >> 5, cc = idx & 31;
            Xs[cc][r] = g_x3[(size_t)(row0 + r) * CC + c0 + cc];
        }
        for (int idx = tid; idx < KK * 32; idx += 256) {
            int k = idx >> 5, cc = idx & 31;
            Ws[k][cc] = drop_w[(size_t)k * CC + c0 + cc];
        }
        __syncthreads();
        #pragma unroll
        for (int si = 0; si < 5; si++) {
            int o = tid + si * 256;
            if (o < KK * 64) {
                int k = o >> 6, r = o & 63;
                float a = acc[si];
                #pragma unroll 8
                for (int cc = 0; cc < 32; cc++) a += Ws[k][cc] * Xs[cc][r];
                acc[si] = a;
            }
        }
        __syncthreads();
    }
    #pragma unroll
    for (int si = 0; si < 5; si++) {
        int o = tid + si * 256;
        if (o < KK * 64) {
            int k = o >> 6, r = o & 63;
            out[((size_t)b * KK + k) * HW + hw0 + r] = acc[si];
        }
    }
}

// ---------------- launch (multi-stream graph) ----------------
#define GSA(p, s) cudaGetSymbolAddress((void**)&p, s)
extern "C" void kernel_launch(void* const* d_in, const int* in_sizes, int n_in,
                              void* d_out, int out_size) {
    const float* M_1   = (const float*)d_in[0];
    const float* F     = (const float*)d_in[1];
    const float* I     = (const float*)d_in[2];
    const float* R     = (const float*)d_in[3];
    const float* lg_w1 = (const float*)d_in[4];
    const float* lg_w2 = (const float*)d_in[5];
    const float* fuse_w= (const float*)d_in[6];
    const float* fuse_b= (const float*)d_in[7];
    const float* q_w   = (const float*)d_in[8];
    const float* q_b   = (const float*)d_in[9];
    const float* k_w   = (const float*)d_in[10];
    const float* k_b   = (const float*)d_in[11];
    const float* v_w   = (const float*)d_in[12];
    const float* v_b   = (const float*)d_in[13];
    const float* c1_w  = (const float*)d_in[14];
    const float* bn1_g = (const float*)d_in[15];
    const float* bn1_b = (const float*)d_in[16];
    const float* c2_w  = (const float*)d_in[17];
    const float* bn2_g = (const float*)d_in[18];
    const float* bn2_b = (const float*)d_in[19];
    const float* c3_w  = (const float*)d_in[20];
    const float* bn3_g = (const float*)d_in[21];
    const float* bn3_b = (const float*)d_in[22];
    const float* drop_w= (const float*)d_in[23];
    float* out = (float*)d_out;

    float *p_Fnhwc, *p_Fg, *p_q, *p_k, *p_v, *p_x3;
    h16 *p_F16, *p_h16, *p_Fl216, *p_Fs16, *p_Fo1b, *p_catb, *p_w2b, *p_w3b;
    h16 *p_qw, *p_kw, *p_lgw, *p_c1;
    GSA(p_Fnhwc, g_Fnhwc); GSA(p_Fg, g_Fg);
    GSA(p_q, g_query); GSA(p_k, g_key); GSA(p_v, g_value); GSA(p_x3, g_x3);
    GSA(p_F16, g_F16); GSA(p_h16, g_h16); GSA(p_Fl216, g_Fl216); GSA(p_Fs16, g_Fs16);
    GSA(p_Fo1b, g_Fo1b); GSA(p_catb, g_catb);
    GSA(p_w2b, g_w2b); GSA(p_w3b, g_w3b);
    GSA(p_qw, g_qw16); GSA(p_kw, g_kw16); GSA(p_lgw, g_lgw16); GSA(p_c1, g_c116);

    static bool init = false;
    static cudaStream_t s1, s2;
    static cudaEvent_t eFork, eTf, eWt, eW2, eM1, eW3, eQ, eFu, eV;
    if (!init) {
        cudaStreamCreateWithFlags(&s1, cudaStreamNonBlocking);
        cudaStreamCreateWithFlags(&s2, cudaStreamNonBlocking);
        cudaEventCreateWithFlags(&eFork, cudaEventDisableTiming);
        cudaEventCreateWithFlags(&eTf,   cudaEventDisableTiming);
        cudaEventCreateWithFlags(&eWt,   cudaEventDisableTiming);
        cudaEventCreateWithFlags(&eW2,   cudaEventDisableTiming);
        cudaEventCreateWithFlags(&eM1,   cudaEventDisableTiming);
        cudaEventCreateWithFlags(&eW3,   cudaEventDisableTiming);
        cudaEventCreateWithFlags(&eQ,    cudaEventDisableTiming);
        cudaEventCreateWithFlags(&eFu,   cudaEventDisableTiming);
        cudaEventCreateWithFlags(&eV,    cudaEventDisableTiming);
        cudaFuncSetAttribute(k_conv_bulk, cudaFuncAttributeMaxDynamicSharedMemorySize, CONVB_SMEM);
        cudaFuncSetAttribute(k_gemm_mma<0>, cudaFuncAttributeMaxDynamicSharedMemorySize, 2 * GSTAGE_B);
        cudaFuncSetAttribute(k_gemm_mma<1>, cudaFuncAttributeMaxDynamicSharedMemorySize, 2 * GSTAGE_B);
        cudaFuncSetAttribute(k_gemm_mma<2>, cudaFuncAttributeMaxDynamicSharedMemorySize, 2 * GSTAGE_B);
        init = true;
    }
    const int GEMM_SMEM = 2 * GSTAGE_B;
    dim3 blk32(32, 8);

    cudaEventRecord(eFork, 0);
    cudaStreamWaitEvent(s1, eFork, 0);
    cudaStreamWaitEvent(s2, eFork, 0);
    k_wt16x<<<dim3(1024, 4), 256, 0, s1>>>(q_w, p_qw, k_w, p_kw, lg_w2, p_lgw, c1_w, p_c1);
    cudaEventRecord(eWt, s1);
    k_wprep<<<(4 * 32 * 19584 + 255) / 256, 256, 0, s1>>>(c2_w, p_w2b, 512, 32);
    cudaEventRecord(eW2, s1);
    k_transpose_m1<<<dim3(HW / 32, 2048 / 32, BATCH), blk32, 0, s1>>>(M_1, p_catb);
    cudaEventRecord(eM1, s1);
    k_wprep<<<(int)(((size_t)4 * 160 * 19584 + 255) / 256), 256, 0, s1>>>(c3_w, p_w3b, 2560, 160);
    cudaEventRecord(eW3, s1);

    k_transpose_f<<<dim3(HW / 32, CC / 32, BATCH), blk32>>>(F, p_Fnhwc, p_F16);
    cudaEventRecord(eTf, 0);
    k_patch_fl<<<BATCH * PP, 256>>>(I, R);
    k_lg1<<<dim3(CC / 64, BATCH * KK), 256>>>(lg_w1);

    cudaStreamWaitEvent(s2, eTf, 0);
    cudaStreamWaitEvent(s2, eWt, 0);
    k_gemm_mma<1><<<dim3(2, 64), 512, GEMM_SMEM, s2>>>(
        p_F16, p_qw, 512, 256, p_q, nullptr, q_b, nullptr, nullptr, nullptr);
    cudaEventRecord(eQ, s2);

    cudaStreamWaitEvent(0, eWt, 0);
    k_gemm_mma<0><<<dim3(4, 19), 512, GEMM_SMEM>>>(
        p_h16, p_lgw, 512, 512, nullptr, p_Fl216, nullptr, nullptr, nullptr, nullptr);
    k_fuse<<<BATCH * KK, CC>>>(fuse_w, fuse_b);
    cudaEventRecord(eFu, 0);
    cudaStreamWaitEvent(s2, eFu, 0);
    k_gemm_v<<<dim3(DD / 64, 2), 256, 0, s2>>>(p_Fg, v_w, p_v, BATCH * KK, DD, CC, v_b);
    cudaEventRecord(eV, s2);

    k_gemm_mma<1><<<dim3(2, 19), 512, GEMM_SMEM>>>(
        p_Fl216, p_kw, 512, 256, p_k, nullptr, k_b, nullptr, nullptr, nullptr);

    cudaStreamWaitEvent(0, eQ, 0);
    cudaStreamWaitEvent(0, eV, 0);
    k_attn<<<BATCH * PP, 256>>>();

    k_gemm_mma<2><<<dim3(4, 64), 512, GEMM_SMEM>>>(
        p_Fs16, p_c1, 256, 512, nullptr, p_Fo1b, nullptr, bn1_g, bn1_b, p_Fnhwc);

    cudaStreamWaitEvent(0, eW2, 0);
    k_conv_bulk<<<dim3(BATCH * 16, 4), 512, CONVB_SMEM>>>(
        p_Fo1b, 32, p_w2b, bn2_g, bn2_b, nullptr, p_catb);
    cudaStreamWaitEvent(0, eM1, 0);
    cudaStreamWaitEvent(0, eW3, 0);
    k_conv_bulk<<<dim3(BATCH * 16, 4), 512, CONVB_SMEM>>>(
        p_catb, 160, p_w3b, bn3_g, bn3_b, p_x3, nullptr);

    k_classifier<<<(BATCH * HW) / 64, 256>>>(drop_w, out);
}

// round 16
// speedup vs baseline: 1.1236x; 1.1236x over previous
#include <cuda_runtime.h>
#include <cuda_fp16.h>
#include <mma.h>
#include <math.h>
#include <stdint.h>

using namespace nvcuda;
typedef __half h16;

#define EPS 1e-5f
#define BATCH 4
#define HH 64
#define WW 64
#define HW 4096
#define BHW 16384
#define CC 512
#define KK 19
#define PP 64
#define NN 64
#define DD 256

__device__ float g_Fnhwc[BATCH * HW * CC];
__device__ float g_Fl[BATCH * PP * KK * CC];
__device__ float g_Fg[BATCH * KK * CC];
__device__ float g_query[BATCH * HW * DD];
__device__ float g_key[BATCH * PP * KK * DD];
__device__ float g_value[BATCH * KK * DD];
__device__ float g_x3[BATCH * HW * CC];
__device__ float g_x3p[BATCH * HW * CC];   // conv3 partial sums

__device__ h16 g_F16[BATCH * HW * CC];
__device__ h16 g_h16[BATCH * PP * KK * CC];
__device__ h16 g_Fl216[BATCH * PP * KK * CC];
__device__ h16 g_Fs16[BATCH * HW * DD];
__device__ h16 g_Fo1b[32 * BHW * 16];
__device__ h16 g_catb[(size_t)160 * BHW * 16];

__device__ h16 g_w2b[4 * 32 * 19584];
__device__ h16 g_w3b[(size_t)4 * 160 * 19584];
__device__ h16 g_qw16[512 * 256];
__device__ h16 g_kw16[512 * 256];
__device__ h16 g_lgw16[512 * 512];
__device__ h16 g_c116[256 * 512];

__device__ __forceinline__ void cpa16(void* sdst, const void* gsrc) {
    unsigned int s = (unsigned int)__cvta_generic_to_shared(sdst);
    asm volatile("cp.async.cg.shared.global [%0], [%1], 16;" :: "r"(s), "l"(gsrc));
}
__device__ __forceinline__ void cpa_commit() { asm volatile("cp.async.commit_group;"); }
template <int N>
__device__ __forceinline__ void cpa_wait() { asm volatile("cp.async.wait_group %0;" :: "n"(N)); }

__device__ __forceinline__ void bulk_cp(unsigned int sdst, const void* gsrc,
                                        unsigned int bytes, unsigned int mbar) {
    asm volatile(
        "cp.async.bulk.shared::cta.global.mbarrier::complete_tx::bytes [%0], [%1], %2, [%3];"
        :: "r"(sdst), "l"(gsrc), "r"(bytes), "r"(mbar) : "memory");
}
__device__ __forceinline__ void mbar_init(unsigned int m, unsigned int c) {
    asm volatile("mbarrier.init.shared.b64 [%0], %1;" :: "r"(m), "r"(c) : "memory");
}
__device__ __forceinline__ void mbar_expect(unsigned int m, unsigned int tx) {
    asm volatile("mbarrier.arrive.expect_tx.shared.b64 _, [%0], %1;" :: "r"(m), "r"(tx) : "memory");
}
__device__ __forceinline__ void mbar_wait(unsigned int m, unsigned int par) {
    unsigned int done;
    asm volatile(
        "{\n\t.reg .pred p;\n\t"
        "mbarrier.try_wait.parity.acquire.cta.shared::cta.b64 p, [%1], %2;\n\t"
        "selp.b32 %0, 1, 0, p;\n\t}" : "=r"(done) : "r"(m), "r"(par) : "memory");
    if (!done) {
        asm volatile(
            "{\n\t.reg .pred P1;\n\tWL_%=:\n\t"
            "mbarrier.try_wait.parity.acquire.cta.shared::cta.b64 P1, [%0], %1, 0x989680;\n\t"
            "@P1 bra.uni WD_%=;\n\tbra.uni WL_%=;\n\tWD_%=:\n\t}"
            :: "r"(m), "r"(par) : "memory");
    }
}

// ---------------- transposes / preps ----------------
__global__ void k_transpose_f(const float* __restrict__ in, float* __restrict__ out,
                              h16* __restrict__ o16) {
    __shared__ float tile[32][33];
    int b = blockIdx.z, hw0 = blockIdx.x * 32, c0 = blockIdx.y * 32;
    int tx = threadIdx.x, ty = threadIdx.y;
    for (int i = ty; i < 32; i += 8)
        tile[i][tx] = in[((size_t)b * CC + c0 + i) * HW + hw0 + tx];
    __syncthreads();
    for (int i = ty; i < 32; i += 8) {
        float v = tile[tx][i];
        size_t o = ((size_t)b * HW + hw0 + i) * CC + c0 + tx;
        out[o] = v;
        o16[o] = __float2half(v);
    }
}
__global__ void k_transpose_m1(const float* __restrict__ in, h16* __restrict__ ob) {
    __shared__ float tile[32][33];
    int b = blockIdx.z, hw0 = blockIdx.x * 32, c0 = blockIdx.y * 32;
    int tx = threadIdx.x, ty = threadIdx.y;
    for (int i = ty; i < 32; i += 8)
        tile[i][tx] = in[((size_t)b * 2048 + c0 + i) * HW + hw0 + tx];
    __syncthreads();
    for (int i = ty; i < 32; i += 8) {
        int cg = 512 + c0 + tx;
        size_t o = ((size_t)(cg >> 4) * BHW + (size_t)b * HW + hw0 + i) * 16 + (cg & 15);
        ob[o] = __float2half(tile[tx][i]);
    }
}
__global__ void k_wprep(const float* __restrict__ w, h16* __restrict__ dst,
                        int Cin, int csteps) {
    size_t d = (size_t)blockIdx.x * 256 + threadIdx.x;
    size_t total = (size_t)4 * csteps * 19584;
    if (d >= total) return;
    int oc = d % 136;
    size_t r = d / 136;
    int k = r % 16; r /= 16;
    int tap = r % 9; r /= 9;
    int ch = r % csteps;
    int nt = r / csteps;
    h16 outv = __float2half(0.f);
    if (oc < 128)
        outv = __float2half(w[((size_t)(nt * 128 + oc) * Cin + ch * 16 + k) * 9 + tap]);
    dst[d] = outv;
}
__global__ void k_wt16x(const float* __restrict__ w0, h16* __restrict__ o0,
                        const float* __restrict__ w1, h16* __restrict__ o1,
                        const float* __restrict__ w2, h16* __restrict__ o2,
                        const float* __restrict__ w3, h16* __restrict__ o3) {
    int which = blockIdx.y;
    const float* w = which == 0 ? w0 : which == 1 ? w1 : which == 2 ? w2 : w3;
    h16* o = which == 0 ? o0 : which == 1 ? o1 : which == 2 ? o2 : o3;
    int K = which == 3 ? 256 : 512;
    int N = which == 2 ? 512 : which == 3 ? 512 : 256;
    int d = blockIdx.x * 256 + threadIdx.x;
    if (d >= K * N) return;
    int k = d / N, n = d % N;
    o[d] = __float2half(w[(size_t)n * K + k]);
}

// ---------------- patch softmax + F_l ----------------
__global__ void k_patch_fl(const float* __restrict__ I, const float* __restrict__ R) {
    int bp = blockIdx.x, b = bp >> 6, p = bp & 63;
    int ph = p >> 3, pw = p & 7, tid = threadIdx.x;
    __shared__ float lg[KK][NN];
    __shared__ float pix[NN][20];
    __shared__ float bc[KK];
    __shared__ float Fp[NN][65];
    for (int idx = tid; idx < KK * NN; idx += 256) {
        int k = idx / NN, n = idx % NN;
        int h = ph * 8 + (n >> 3), w = pw * 8 + (n & 7);
        lg[k][n] = I[(((size_t)b * KK + k) * HH + h) * WW + w];
    }
    if (tid < KK) bc[tid] = R[((size_t)b * KK + tid) * PP + p];
    __syncthreads();
    if (tid < KK) {
        float mx = -1e30f;
        for (int n = 0; n < NN; n++) mx = fmaxf(mx, lg[tid][n]);
        float s = 0.f;
        for (int n = 0; n < NN; n++) { float e = __expf(lg[tid][n] - mx); pix[n][tid] = e; s += e; }
        float inv = 1.f / s;
        for (int n = 0; n < NN; n++) pix[n][tid] *= inv;
    }
    __syncthreads();
    for (int c0 = 0; c0 < CC; c0 += 64) {
        for (int idx = tid; idx < NN * 64; idx += 256) {
            int n = idx >> 6, cc = idx & 63;
            int h = ph * 8 + (n >> 3), w = pw * 8 + (n & 7);
            Fp[n][cc] = g_Fnhwc[((size_t)b * HW + h * WW + w) * CC + c0 + cc];
        }
        __syncthreads();
        for (int o = tid; o < KK * 64; o += 256) {
            int k = o >> 6, cc = o & 63;
            float acc = 0.f;
            #pragma unroll 8
            for (int n = 0; n < NN; n++) acc += pix[n][k] * Fp[n][cc];
            g_Fl[((size_t)bp * KK + k) * CC + c0 + cc] = acc * bc[k];
        }
        __syncthreads();
    }
}

__global__ void k_lg1(const float* __restrict__ lg_w1) {
    int c0 = blockIdx.x * 64, bk = blockIdx.y;
    int b = bk / KK, k = bk % KK, tid = threadIdx.x;
    __shared__ float w1[64][64];
    __shared__ float Fl[64][65];
    for (int idx = tid; idx < 4096; idx += 256) w1[idx >> 6][idx & 63] = lg_w1[idx];
    for (int idx = tid; idx < 4096; idx += 256) {
        int p = idx >> 6, cc = idx & 63;
        Fl[p][cc] = g_Fl[(((size_t)b * PP + p) * KK + k) * CC + c0 + cc];
    }
    __syncthreads();
    for (int o = tid; o < 4096; o += 256) {
        int q = o >> 6, cc = o & 63;
        float acc = Fl[q][cc];
        #pragma unroll 8
        for (int p = 0; p < 64; p++) acc += w1[q][p] * Fl[p][cc];
        g_h16[(((size_t)b * PP + q) * KK + k) * CC + c0 + cc] = __float2half(fmaxf(acc, 0.f));
    }
}

__global__ void k_gemm_v(const float* __restrict__ A, const float* __restrict__ Bw,
                         float* __restrict__ C, int M, int N, int K,
                         const float* __restrict__ bias) {
    __shared__ float As[16][68];
    __shared__ float Bs[16][68];
    int m0 = blockIdx.y * 64, n0 = blockIdx.x * 64, tid = threadIdx.x;
    int tx = tid & 15, ty = tid >> 4;
    float acc[4][4] = {};
    for (int k0 = 0; k0 < K; k0 += 16) {
        for (int idx = tid; idx < 1024; idx += 256) {
            int i = idx >> 4, kk = idx & 15;
            int m = m0 + i;
            As[kk][i] = (m < M) ? A[(size_t)m * K + k0 + kk] : 0.f;
        }
        for (int idx = tid; idx < 1024; idx += 256) {
            int j = idx >> 4, kk = idx & 15;
            Bs[kk][j] = Bw[(size_t)(n0 + j) * K + k0 + kk];
        }
        __syncthreads();
        #pragma unroll
        for (int kk = 0; kk < 16; kk++) {
            float a[4], bv[4];
            #pragma unroll
            for (int i = 0; i < 4; i++) a[i] = As[kk][ty * 4 + i];
            #pragma unroll
            for (int j = 0; j < 4; j++) bv[j] = Bs[kk][tx * 4 + j];
            #pragma unroll
            for (int i = 0; i < 4; i++)
                #pragma unroll
                for (int j = 0; j < 4; j++) acc[i][j] += a[i] * bv[j];
        }
        __syncthreads();
    }
    #pragma unroll
    for (int i = 0; i < 4; i++) {
        int m = m0 + ty * 4 + i;
        if (m >= M) continue;
        #pragma unroll
        for (int j = 0; j < 4; j++)
            C[(size_t)m * N + n0 + tx * 4 + j] = acc[i][j] + bias[n0 + tx * 4 + j];
    }
}

__global__ void k_fuse(const float* __restrict__ fw, const float* __restrict__ fb) {
    int bk = blockIdx.x, c = threadIdx.x;
    int b = bk / KK, k = bk % KK;
    float acc = fb[0];
    #pragma unroll 8
    for (int p = 0; p < PP; p++)
        acc += fw[p] * __half2float(g_Fl216[(((size_t)b * PP + p) * KK + k) * CC + c]);
    g_Fg[(size_t)bk * CC + c] = acc;
}

__global__ void k_attn() {
    int bp = blockIdx.x, b = bp >> 6, p = bp & 63;
    int ph = p >> 3, pw = p & 7, tid = threadIdx.x;
    __shared__ float ks[KK][DD];
    __shared__ float vs[KK][DD];
    for (int idx = tid; idx < KK * DD; idx += 256)
        ((float*)ks)[idx] = g_key[(size_t)bp * KK * DD + idx];
    for (int idx = tid; idx < KK * DD; idx += 256)
        ((float*)vs)[idx] = g_value[(size_t)b * KK * DD + idx];
    __syncthreads();
    int warp = tid >> 5, lane = tid & 31;
    for (int n = warp; n < NN; n += 8) {
        int h = ph * 8 + (n >> 3), w = pw * 8 + (n & 7);
        const float* qrow = &g_query[((size_t)b * HW + h * WW + w) * DD];
        float qr[8];
        #pragma unroll
        for (int i = 0; i < 8; i++) qr[i] = qrow[i * 32 + lane];
        float acc[KK];
        #pragma unroll
        for (int k = 0; k < KK; k++) acc[k] = 0.f;
        #pragma unroll
        for (int i = 0; i < 8; i++) {
            float qd = qr[i];
            #pragma unroll
            for (int k = 0; k < KK; k++) acc[k] += qd * ks[k][i * 32 + lane];
        }
        #pragma unroll
        for (int k = 0; k < KK; k++)
            #pragma unroll
            for (int off = 16; off > 0; off >>= 1)
                acc[k] += __shfl_xor_sync(0xFFFFFFFFu, acc[k], off);
        float mx = -1e30f;
        #pragma unroll
        for (int k = 0; k < KK; k++) mx = fmaxf(mx, acc[k]);
        float sum = 0.f;
        #pragma unroll
        for (int k = 0; k < KK; k++) { acc[k] = __expf(acc[k] - mx); sum += acc[k]; }
        float inv = 1.f / sum;
        #pragma unroll
        for (int k = 0; k < KK; k++) acc[k] *= inv;
        size_t ob = ((size_t)b * HW + h * WW + w) * DD;
        #pragma unroll
        for (int i = 0; i < 8; i++) {
            int d = i * 32 + lane;
            float o = 0.f;
            #pragma unroll
            for (int k = 0; k < KK; k++) o += acc[k] * vs[k][d];
            g_Fs16[ob + d] = __float2half(o);
        }
    }
}

// ---------------- 1-term fp16 wmma GEMM ----------------
#define GSTAGE_B 12544
template <int MODE>
__global__ __launch_bounds__(512)
void k_gemm_mma(const h16* __restrict__ Ag, const h16* __restrict__ Wt,
                int K, int N,
                float* __restrict__ Cf, h16* __restrict__ C16,
                const float* __restrict__ bias,
                const float* __restrict__ bng, const float* __restrict__ bnb,
                const float* __restrict__ resid) {
    extern __shared__ char smem[];
    int n0 = blockIdx.x * 128, m0 = blockIdx.y * 256;
    int tid = threadIdx.x, lane = tid & 31, warp = tid >> 5;
    int warpM = warp >> 1, warpN = warp & 1;
    int iters = K >> 4;

    wmma::fragment<wmma::accumulator, 16, 16, 16, float> acc[2][4];
    #pragma unroll
    for (int mt = 0; mt < 2; mt++)
        #pragma unroll
        for (int nj = 0; nj < 4; nj++) wmma::fill_fragment(acc[mt][nj], 0.f);

    auto issue = [&](int it) {
        int k0 = it << 4;
        char* base = smem + (it & 1) * GSTAGE_B;
        h16* As = (h16*)base;
        h16* Ws = (h16*)(base + 8192);
        {
            int flat = tid * 8;
            int r = flat >> 4, c8 = flat & 15;
            cpa16(As + flat, Ag + (size_t)(m0 + r) * K + k0 + c8);
        }
        if (tid < 256) {
            int flat = tid * 8;
            int kk = flat >> 7, n8 = flat & 127;
            cpa16(Ws + kk * 136 + n8, Wt + (size_t)(k0 + kk) * N + n0 + n8);
        }
        cpa_commit();
    };

    issue(0);
    for (int it = 0; it < iters; it++) {
        cpa_wait<0>();
        __syncthreads();
        if (it + 1 < iters) issue(it + 1);
        char* base = smem + (it & 1) * GSTAGE_B;
        h16* As = (h16*)base;
        h16* Ws = (h16*)(base + 8192);
        #pragma unroll
        for (int mt = 0; mt < 2; mt++) {
            int t = warpM * 2 + mt;
            wmma::fragment<wmma::matrix_a, 16, 16, 16, h16, wmma::row_major> af;
            wmma::load_matrix_sync(af, As + t * 256, 16);
            #pragma unroll
            for (int nj = 0; nj < 4; nj++) {
                wmma::fragment<wmma::matrix_b, 16, 16, 16, h16, wmma::row_major> bf;
                wmma::load_matrix_sync(bf, Ws + warpN * 64 + nj * 16, 136);
                wmma::mma_sync(acc[mt][nj], af, bf, acc[mt][nj]);
            }
        }
        __syncthreads();
    }

    float* buf = (float*)smem + warp * 320;
    #pragma unroll
    for (int mt = 0; mt < 2; mt++) {
        int t = warpM * 2 + mt;
        #pragma unroll
        for (int nj = 0; nj < 4; nj++) {
            wmma::store_matrix_sync(buf, acc[mt][nj], 20, wmma::mem_row_major);
            __syncwarp();
            #pragma unroll
            for (int l = 0; l < 8; l++) {
                int e = l * 32 + lane;
                int r = e >> 4, c = e & 15;
                int gm = m0 + t * 16 + r;
                int gn = n0 + warpN * 64 + nj * 16 + c;
                float v = buf[r * 20 + c];
                size_t o = (size_t)gm * N + gn;
                if (MODE == 0) {
                    C16[o] = __float2half(v);
                } else if (MODE == 1) {
                    Cf[o] = v + bias[gn];
                } else {
                    float s = bng[gn] * rsqrtf(1.f + EPS);
                    v = resid[o] + fmaxf(v * s + bnb[gn], 0.f);
                    C16[((size_t)(gn >> 4) * BHW + gm) * 16 + (gn & 15)] = __float2half(v);
                }
            }
            __syncwarp();
        }
    }
}

// ---------------- bulk-copy conv (R14 staging), 3-stage; splittable over chunks ----------------
// pin: partial input (fp32 NHWC, added pre-BN); praw: raw fp32 partial output (skips BN)
#define SW_OFF 12672
#define CSTG 51840
#define CONVB_SMEM (3 * CSTG + 64)
__global__ __launch_bounds__(512, 1)
void k_conv_bulk(const h16* __restrict__ inb, int csteps, int cstride, int coff,
                 const h16* __restrict__ wb,
                 const float* __restrict__ bng, const float* __restrict__ bnb,
                 float* __restrict__ out_f, h16* __restrict__ ob,
                 const float* __restrict__ pin, float* __restrict__ praw) {
    extern __shared__ char dsm[];
    char* aptr = (char*)(((size_t)dsm + 127) & ~(size_t)127);
    unsigned int abase = (unsigned int)__cvta_generic_to_shared(aptr);
    unsigned int mbs = abase + 3 * CSTG;

    int tid = threadIdx.x, lane = tid & 31, warp = tid >> 5;
    int warpM = warp >> 1, warpN = warp & 1;
    int b = blockIdx.x >> 4, h0 = (blockIdx.x & 15) << 2;
    int nt = blockIdx.y;
    int oc0 = nt << 7;

    if (tid < 3) mbar_init(mbs + tid * 8, 1);
    if (tid < 18) {
        int r = tid % 6, bufi = tid / 6;
        char* rowp = aptr + bufi * CSTG + r * 2112;
        int grow = h0 + r - 1;
        if (grow < 0 || grow >= HH) {
            for (int i = 0; i < 132; i++) ((float4*)rowp)[i] = make_float4(0, 0, 0, 0);
        } else {
            ((float4*)rowp)[0] = make_float4(0, 0, 0, 0);
            ((float4*)rowp)[1] = make_float4(0, 0, 0, 0);
            ((float4*)(rowp + 2080))[0] = make_float4(0, 0, 0, 0);
            ((float4*)(rowp + 2080))[1] = make_float4(0, 0, 0, 0);
        }
    }
    __syncthreads();

    int nvalid = 0;
    for (int r = 0; r < 6; r++) { int g = h0 + r - 1; if (g >= 0 && g < HH) nvalid++; }
    unsigned int txb = 39168u + (unsigned int)nvalid * 2048u;

    auto issue = [&](int s) {
        int bi = s % 3;
        unsigned int base = abase + bi * CSTG;
        unsigned int mb = mbs + bi * 8;
        mbar_expect(mb, txb);
        bulk_cp(base + SW_OFF, wb + (size_t)(nt * cstride + coff + s) * 19584, 39168, mb);
        for (int r = 0; r < 6; r++) {
            int grow = h0 + r - 1;
            if (grow < 0 || grow >= HH) continue;
            size_t so = ((size_t)(s * BATCH + b) * HH + grow) * WW * 16;
            bulk_cp(base + r * 2112 + 32, inb + so, 2048, mb);
        }
    };

    if (tid == 0) {
        issue(0);
        if (csteps > 1) issue(1);
        if (csteps > 2) issue(2);
    }
    int ph[3] = {0, 0, 0};

    wmma::fragment<wmma::accumulator, 16, 16, 16, float> acc[2][4];
    #pragma unroll
    for (int mt = 0; mt < 2; mt++)
        #pragma unroll
        for (int nj = 0; nj < 4; nj++) wmma::fill_fragment(acc[mt][nj], 0.f);

    for (int s = 0; s < csteps; s++) {
        int bi = s % 3;
        mbar_wait(mbs + bi * 8, ph[bi]); ph[bi] ^= 1;
        char* base = aptr + bi * CSTG;
        h16* As = (h16*)base;
        h16* Ws = (h16*)(base + SW_OFF);

        #pragma unroll
        for (int tap = 0; tap < 9; tap++) {
            int ky = tap / 3, kx = tap % 3;
            wmma::fragment<wmma::matrix_a, 16, 16, 16, h16, wmma::row_major> af[2];
            #pragma unroll
            for (int mt = 0; mt < 2; mt++) {
                int t = warpM * 2 + mt;
                int row_l = t >> 2, px0 = (t & 3) * 16;
                wmma::load_matrix_sync(af[mt], As + ((row_l + ky) * 66 + px0 + kx) * 16, 16);
            }
            #pragma unroll
            for (int nj = 0; nj < 4; nj++) {
                wmma::fragment<wmma::matrix_b, 16, 16, 16, h16, wmma::row_major> bf;
                wmma::load_matrix_sync(bf, Ws + tap * 2176 + warpN * 64 + nj * 16, 136);
                #pragma unroll
                for (int mt = 0; mt < 2; mt++)
                    wmma::mma_sync(acc[mt][nj], af[mt], bf, acc[mt][nj]);
            }
        }
        __syncthreads();
        if (tid == 0 && s + 3 < csteps) issue(s + 3);
    }

    float* buf = (float*)aptr + warp * 320;
    #pragma unroll
    for (int mt = 0; mt < 2; mt++) {
        int t = warpM * 2 + mt;
        int row_l = t >> 2, px0 = (t & 3) * 16;
        int grow = h0 + row_l;
        #pragma unroll
        for (int nj = 0; nj < 4; nj++) {
            wmma::store_matrix_sync(buf, acc[mt][nj], 20, wmma::mem_row_major);
            __syncwarp();
            #pragma unroll
            for (int l = 0; l < 8; l++) {
                int e = l * 32 + lane;
                int r = e >> 4, c = e & 15;
                int gn = oc0 + warpN * 64 + nj * 16 + c;
                int pix = (b * HH + grow) * WW + px0 + r;
                float v = buf[r * 20 + c];
                if (praw) {
                    praw[(size_t)pix * CC + gn] = v;
                } else {
                    if (pin) v += pin[(size_t)pix * CC + gn];
                    float sc = bng[gn] * rsqrtf(1.f + EPS);
                    v = fmaxf(v * sc + bnb[gn], 0.f);
                    if (out_f) out_f[(size_t)pix * CC + gn] = v;
                    else ob[((size_t)(gn >> 4) * BHW + pix) * 16 + (gn & 15)] = __float2half(v);
                }
            }
            __syncwarp();
        }
    }
}

// ---------------- classifier ----------------
__global__ void k_classifier(const float* __restrict__ drop_w, float* __restrict__ out) {
    __shared__ float Xs[32][65];
    __shared__ float Ws[KK][33];
    int tid = threadIdx.x;
    int row0 = blockIdx.x * 64;
    int b = row0 >> 12, hw0 = row0 & 4095;
    float acc[5] = {0.f, 0.f, 0.f, 0.f, 0.f};
    for (int c0 = 0; c0 < CC; c0 += 32) {
        for (int idx = tid; idx < 2048; idx += 256) {
            int r = idx >> 5, cc = idx & 31;
            Xs[cc][r] = g_x3[(size_t)(row0 + r) * CC + c0 + cc];
        }
        for (int idx = tid; idx < KK * 32; idx += 256) {
            int k = idx >> 5, cc = idx & 31;
            Ws[k][cc] = drop_w[(size_t)k * CC + c0 + cc];
        }
        __syncthreads();
        #pragma unroll
        for (int si = 0; si < 5; si++) {
            int o = tid + si * 256;
            if (o < KK * 64) {
                int k = o >> 6, r = o & 63;
                float a = acc[si];
                #pragma unroll 8
                for (int cc = 0; cc < 32; cc++) a += Ws[k][cc] * Xs[cc][r];
                acc[si] = a;
            }
        }
        __syncthreads();
    }
    #pragma unroll
    for (int si = 0; si < 5; si++) {
        int o = tid + si * 256;
        if (o < KK * 64) {
            int k = o >> 6, r = o & 63;
            out[((size_t)b * KK + k) * HW + hw0 + r] = acc[si];
        }
    }
}

// ---------------- launch (multi-stream graph) ----------------
#define GSA(p, s) cudaGetSymbolAddress((void**)&p, s)
extern "C" void kernel_launch(void* const* d_in, const int* in_sizes, int n_in,
                              void* d_out, int out_size) {
    const float* M_1   = (const float*)d_in[0];
    const float* F     = (const float*)d_in[1];
    const float* I     = (const float*)d_in[2];
    const float* R     = (const float*)d_in[3];
    const float* lg_w1 = (const float*)d_in[4];
    const float* lg_w2 = (const float*)d_in[5];
    const float* fuse_w= (const float*)d_in[6];
    const float* fuse_b= (const float*)d_in[7];
    const float* q_w   = (const float*)d_in[8];
    const float* q_b   = (const float*)d_in[9];
    const float* k_w   = (const float*)d_in[10];
    const float* k_b   = (const float*)d_in[11];
    const float* v_w   = (const float*)d_in[12];
    const float* v_b   = (const float*)d_in[13];
    const float* c1_w  = (const float*)d_in[14];
    const float* bn1_g = (const float*)d_in[15];
    const float* bn1_b = (const float*)d_in[16];
    const float* c2_w  = (const float*)d_in[17];
    const float* bn2_g = (const float*)d_in[18];
    const float* bn2_b = (const float*)d_in[19];
    const float* c3_w  = (const float*)d_in[20];
    const float* bn3_g = (const float*)d_in[21];
    const float* bn3_b = (const float*)d_in[22];
    const float* drop_w= (const float*)d_in[23];
    float* out = (float*)d_out;

    float *p_Fnhwc, *p_Fg, *p_q, *p_k, *p_v, *p_x3, *p_x3p;
    h16 *p_F16, *p_h16, *p_Fl216, *p_Fs16, *p_Fo1b, *p_catb, *p_w2b, *p_w3b;
    h16 *p_qw, *p_kw, *p_lgw, *p_c1;
    GSA(p_Fnhwc, g_Fnhwc); GSA(p_Fg, g_Fg);
    GSA(p_q, g_query); GSA(p_k, g_key); GSA(p_v, g_value);
    GSA(p_x3, g_x3); GSA(p_x3p, g_x3p);
    GSA(p_F16, g_F16); GSA(p_h16, g_h16); GSA(p_Fl216, g_Fl216); GSA(p_Fs16, g_Fs16);
    GSA(p_Fo1b, g_Fo1b); GSA(p_catb, g_catb);
    GSA(p_w2b, g_w2b); GSA(p_w3b, g_w3b);
    GSA(p_qw, g_qw16); GSA(p_kw, g_kw16); GSA(p_lgw, g_lgw16); GSA(p_c1, g_c116);

    static bool init = false;
    static cudaStream_t s1, s2;
    static cudaEvent_t eFork, eTf, eWt, eW2, eQ, eFu, eV, eC3a;
    if (!init) {
        cudaStreamCreateWithFlags(&s1, cudaStreamNonBlocking);
        cudaStreamCreateWithFlags(&s2, cudaStreamNonBlocking);
        cudaEventCreateWithFlags(&eFork, cudaEventDisableTiming);
        cudaEventCreateWithFlags(&eTf,   cudaEventDisableTiming);
        cudaEventCreateWithFlags(&eWt,   cudaEventDisableTiming);
        cudaEventCreateWithFlags(&eW2,   cudaEventDisableTiming);
        cudaEventCreateWithFlags(&eQ,    cudaEventDisableTiming);
        cudaEventCreateWithFlags(&eFu,   cudaEventDisableTiming);
        cudaEventCreateWithFlags(&eV,    cudaEventDisableTiming);
        cudaEventCreateWithFlags(&eC3a,  cudaEventDisableTiming);
        cudaFuncSetAttribute(k_conv_bulk, cudaFuncAttributeMaxDynamicSharedMemorySize, CONVB_SMEM);
        cudaFuncSetAttribute(k_gemm_mma<0>, cudaFuncAttributeMaxDynamicSharedMemorySize, 2 * GSTAGE_B);
        cudaFuncSetAttribute(k_gemm_mma<1>, cudaFuncAttributeMaxDynamicSharedMemorySize, 2 * GSTAGE_B);
        cudaFuncSetAttribute(k_gemm_mma<2>, cudaFuncAttributeMaxDynamicSharedMemorySize, 2 * GSTAGE_B);
        init = true;
    }
    const int GEMM_SMEM = 2 * GSTAGE_B;
    dim3 blk32(32, 8);

    cudaEventRecord(eFork, 0);
    cudaStreamWaitEvent(s1, eFork, 0);
    cudaStreamWaitEvent(s2, eFork, 0);
    // s1: preps, then conv3a over M1 chunks (overlaps the whole attention chain)
    k_wt16x<<<dim3(1024, 4), 256, 0, s1>>>(q_w, p_qw, k_w, p_kw, lg_w2, p_lgw, c1_w, p_c1);
    cudaEventRecord(eWt, s1);
    k_wprep<<<(4 * 32 * 19584 + 255) / 256, 256, 0, s1>>>(c2_w, p_w2b, 512, 32);
    cudaEventRecord(eW2, s1);
    k_transpose_m1<<<dim3(HW / 32, 2048 / 32, BATCH), blk32, 0, s1>>>(M_1, p_catb);
    k_wprep<<<(int)(((size_t)4 * 160 * 19584 + 255) / 256), 256, 0, s1>>>(c3_w, p_w3b, 2560, 160);
    // conv3a: chunks 32..159 -> raw partials
    k_conv_bulk<<<dim3(BATCH * 16, 4), 512, CONVB_SMEM, s1>>>(
        p_catb + (size_t)32 * BHW * 16, 128, 160, 32, p_w3b,
        nullptr, nullptr, nullptr, nullptr, nullptr, p_x3p);
    cudaEventRecord(eC3a, s1);

    // main chain
    k_transpose_f<<<dim3(HW / 32, CC / 32, BATCH), blk32>>>(F, p_Fnhwc, p_F16);
    cudaEventRecord(eTf, 0);
    k_patch_fl<<<BATCH * PP, 256>>>(I, R);
    k_lg1<<<dim3(CC / 64, BATCH * KK), 256>>>(lg_w1);

    cudaStreamWaitEvent(s2, eTf, 0);
    cudaStreamWaitEvent(s2, eWt, 0);
    k_gemm_mma<1><<<dim3(2, 64), 512, GEMM_SMEM, s2>>>(
        p_F16, p_qw, 512, 256, p_q, nullptr, q_b, nullptr, nullptr, nullptr);
    cudaEventRecord(eQ, s2);

    cudaStreamWaitEvent(0, eWt, 0);
    k_gemm_mma<0><<<dim3(4, 19), 512, GEMM_SMEM>>>(
        p_h16, p_lgw, 512, 512, nullptr, p_Fl216, nullptr, nullptr, nullptr, nullptr);
    k_fuse<<<BATCH * KK, CC>>>(fuse_w, fuse_b);
    cudaEventRecord(eFu, 0);
    cudaStreamWaitEvent(s2, eFu, 0);
    k_gemm_v<<<dim3(DD / 64, 2), 256, 0, s2>>>(p_Fg, v_w, p_v, BATCH * KK, DD, CC, v_b);
    cudaEventRecord(eV, s2);

    k_gemm_mma<1><<<dim3(2, 19), 512, GEMM_SMEM>>>(
        p_Fl216, p_kw, 512, 256, p_k, nullptr, k_b, nullptr, nullptr, nullptr);

    cudaStreamWaitEvent(0, eQ, 0);
    cudaStreamWaitEvent(0, eV, 0);
    k_attn<<<BATCH * PP, 256>>>();

    k_gemm_mma<2><<<dim3(4, 64), 512, GEMM_SMEM>>>(
        p_Fs16, p_c1, 256, 512, nullptr, p_Fo1b, nullptr, bn1_g, bn1_b, p_Fnhwc);

    cudaStreamWaitEvent(0, eW2, 0);
    k_conv_bulk<<<dim3(BATCH * 16, 4), 512, CONVB_SMEM>>>(
        p_Fo1b, 32, 32, 0, p_w2b, bn2_g, bn2_b, nullptr, p_catb, nullptr, nullptr);

    // conv3b: chunks 0..31 + partials -> x3
    cudaStreamWaitEvent(0, eC3a, 0);
    k_conv_bulk<<<dim3(BATCH * 16, 4), 512, CONVB_SMEM>>>(
        p_catb, 32, 160, 0, p_w3b, bn3_g, bn3_b, p_x3, nullptr, p_x3p, nullptr);

    k_classifier<<<(BATCH * HW) / 64, 256>>>(drop_w, out);
}

// round 17
// speedup vs baseline: 1.2014x; 1.0692x over previous
#include <cuda_runtime.h>
#include <cuda_fp16.h>
#include <mma.h>
#include <math.h>
#include <stdint.h>

using namespace nvcuda;
typedef __half h16;

#define EPS 1e-5f
#define BATCH 4
#define HH 64
#define WW 64
#define HW 4096
#define BHW 16384
#define CC 512
#define KK 19
#define PP 64
#define NN 64
#define DD 256

__device__ float g_Fnhwc[BATCH * HW * CC];
__device__ float g_Fl[BATCH * PP * KK * CC];
__device__ float g_Fg[BATCH * KK * CC];
__device__ float g_query[BATCH * HW * DD];
__device__ float g_key[BATCH * PP * KK * DD];
__device__ float g_value[BATCH * KK * DD];
__device__ float g_x3[BATCH * HW * CC];
__device__ float g_x3p[BATCH * HW * CC];

__device__ h16 g_F16[BATCH * HW * CC];
__device__ h16 g_h16[BATCH * PP * KK * CC];
__device__ h16 g_Fl216[BATCH * PP * KK * CC];
__device__ h16 g_Fs16[BATCH * HW * DD];
__device__ h16 g_Fo1b[32 * BHW * 16];
__device__ h16 g_catb[(size_t)160 * BHW * 16];

__device__ h16 g_w2b[4 * 32 * 19584];
__device__ h16 g_w3b[(size_t)4 * 160 * 19584];
__device__ h16 g_qw16[512 * 256];
__device__ h16 g_kw16[512 * 256];
__device__ h16 g_lgw16[512 * 512];
__device__ h16 g_c116[256 * 512];

__device__ __forceinline__ void cpa16(void* sdst, const void* gsrc) {
    unsigned int s = (unsigned int)__cvta_generic_to_shared(sdst);
    asm volatile("cp.async.cg.shared.global [%0], [%1], 16;" :: "r"(s), "l"(gsrc));
}
__device__ __forceinline__ void cpa_commit() { asm volatile("cp.async.commit_group;"); }
template <int N>
__device__ __forceinline__ void cpa_wait() { asm volatile("cp.async.wait_group %0;" :: "n"(N)); }

__device__ __forceinline__ void bulk_cp(unsigned int sdst, const void* gsrc,
                                        unsigned int bytes, unsigned int mbar) {
    asm volatile(
        "cp.async.bulk.shared::cta.global.mbarrier::complete_tx::bytes [%0], [%1], %2, [%3];"
        :: "r"(sdst), "l"(gsrc), "r"(bytes), "r"(mbar) : "memory");
}
__device__ __forceinline__ void mbar_init(unsigned int m, unsigned int c) {
    asm volatile("mbarrier.init.shared.b64 [%0], %1;" :: "r"(m), "r"(c) : "memory");
}
__device__ __forceinline__ void mbar_expect(unsigned int m, unsigned int tx) {
    asm volatile("mbarrier.arrive.expect_tx.shared.b64 _, [%0], %1;" :: "r"(m), "r"(tx) : "memory");
}
__device__ __forceinline__ void mbar_wait(unsigned int m, unsigned int par) {
    unsigned int done;
    asm volatile(
        "{\n\t.reg .pred p;\n\t"
        "mbarrier.try_wait.parity.acquire.cta.shared::cta.b64 p, [%1], %2;\n\t"
        "selp.b32 %0, 1, 0, p;\n\t}" : "=r"(done) : "r"(m), "r"(par) : "memory");
    if (!done) {
        asm volatile(
            "{\n\t.reg .pred P1;\n\tWL_%=:\n\t"
            "mbarrier.try_wait.parity.acquire.cta.shared::cta.b64 P1, [%0], %1, 0x989680;\n\t"
            "@P1 bra.uni WD_%=;\n\tbra.uni WL_%=;\n\tWD_%=:\n\t}"
            :: "r"(m), "r"(par) : "memory");
    }
}

// ---------------- transposes / preps ----------------
__global__ void k_transpose_f(const float* __restrict__ in, float* __restrict__ out,
                              h16* __restrict__ o16) {
    __shared__ float tile[32][33];
    int b = blockIdx.z, hw0 = blockIdx.x * 32, c0 = blockIdx.y * 32;
    int tx = threadIdx.x, ty = threadIdx.y;
    for (int i = ty; i < 32; i += 8)
        tile[i][tx] = in[((size_t)b * CC + c0 + i) * HW + hw0 + tx];
    __syncthreads();
    for (int i = ty; i < 32; i += 8) {
        float v = tile[tx][i];
        size_t o = ((size_t)b * HW + hw0 + i) * CC + c0 + tx;
        out[o] = v;
        o16[o] = __float2half(v);
    }
}
__global__ void k_transpose_m1(const float* __restrict__ in, h16* __restrict__ ob) {
    __shared__ float tile[32][33];
    int b = blockIdx.z, hw0 = blockIdx.x * 32, c0 = blockIdx.y * 32;
    int tx = threadIdx.x, ty = threadIdx.y;
    for (int i = ty; i < 32; i += 8)
        tile[i][tx] = in[((size_t)b * 2048 + c0 + i) * HW + hw0 + tx];
    __syncthreads();
    for (int i = ty; i < 32; i += 8) {
        int cg = 512 + c0 + tx;
        size_t o = ((size_t)(cg >> 4) * BHW + (size_t)b * HW + hw0 + i) * 16 + (cg & 15);
        ob[o] = __float2half(tile[tx][i]);
    }
}
__global__ void k_wprep(const float* __restrict__ w, h16* __restrict__ dst,
                        int Cin, int csteps) {
    size_t d = (size_t)blockIdx.x * 256 + threadIdx.x;
    size_t total = (size_t)4 * csteps * 19584;
    if (d >= total) return;
    int oc = d % 136;
    size_t r = d / 136;
    int k = r % 16; r /= 16;
    int tap = r % 9; r /= 9;
    int ch = r % csteps;
    int nt = r / csteps;
    h16 outv = __float2half(0.f);
    if (oc < 128)
        outv = __float2half(w[((size_t)(nt * 128 + oc) * Cin + ch * 16 + k) * 9 + tap]);
    dst[d] = outv;
}
__global__ void k_wt16x(const float* __restrict__ w0, h16* __restrict__ o0,
                        const float* __restrict__ w1, h16* __restrict__ o1,
                        const float* __restrict__ w2, h16* __restrict__ o2,
                        const float* __restrict__ w3, h16* __restrict__ o3) {
    int which = blockIdx.y;
    const float* w = which == 0 ? w0 : which == 1 ? w1 : which == 2 ? w2 : w3;
    h16* o = which == 0 ? o0 : which == 1 ? o1 : which == 2 ? o2 : o3;
    int K = which == 3 ? 256 : 512;
    int N = which == 2 ? 512 : which == 3 ? 512 : 256;
    int d = blockIdx.x * 256 + threadIdx.x;
    if (d >= K * N) return;
    int k = d / N, n = d % N;
    o[d] = __float2half(w[(size_t)n * K + k]);
}

// ---------------- patch softmax + F_l ----------------
__global__ void k_patch_fl(const float* __restrict__ I, const float* __restrict__ R) {
    int bp = blockIdx.x, b = bp >> 6, p = bp & 63;
    int ph = p >> 3, pw = p & 7, tid = threadIdx.x;
    __shared__ float lg[KK][NN];
    __shared__ float pix[NN][20];
    __shared__ float bc[KK];
    __shared__ float Fp[NN][65];
    for (int idx = tid; idx < KK * NN; idx += 256) {
        int k = idx / NN, n = idx % NN;
        int h = ph * 8 + (n >> 3), w = pw * 8 + (n & 7);
        lg[k][n] = I[(((size_t)b * KK + k) * HH + h) * WW + w];
    }
    if (tid < KK) bc[tid] = R[((size_t)b * KK + tid) * PP + p];
    __syncthreads();
    if (tid < KK) {
        float mx = -1e30f;
        for (int n = 0; n < NN; n++) mx = fmaxf(mx, lg[tid][n]);
        float s = 0.f;
        for (int n = 0; n < NN; n++) { float e = __expf(lg[tid][n] - mx); pix[n][tid] = e; s += e; }
        float inv = 1.f / s;
        for (int n = 0; n < NN; n++) pix[n][tid] *= inv;
    }
    __syncthreads();
    for (int c0 = 0; c0 < CC; c0 += 64) {
        for (int idx = tid; idx < NN * 64; idx += 256) {
            int n = idx >> 6, cc = idx & 63;
            int h = ph * 8 + (n >> 3), w = pw * 8 + (n & 7);
            Fp[n][cc] = g_Fnhwc[((size_t)b * HW + h * WW + w) * CC + c0 + cc];
        }
        __syncthreads();
        for (int o = tid; o < KK * 64; o += 256) {
            int k = o >> 6, cc = o & 63;
            float acc = 0.f;
            #pragma unroll 8
            for (int n = 0; n < NN; n++) acc += pix[n][k] * Fp[n][cc];
            g_Fl[((size_t)bp * KK + k) * CC + c0 + cc] = acc * bc[k];
        }
        __syncthreads();
    }
}

__global__ void k_lg1(const float* __restrict__ lg_w1) {
    int c0 = blockIdx.x * 64, bk = blockIdx.y;
    int b = bk / KK, k = bk % KK, tid = threadIdx.x;
    __shared__ float w1[64][64];
    __shared__ float Fl[64][65];
    for (int idx = tid; idx < 4096; idx += 256) w1[idx >> 6][idx & 63] = lg_w1[idx];
    for (int idx = tid; idx < 4096; idx += 256) {
        int p = idx >> 6, cc = idx & 63;
        Fl[p][cc] = g_Fl[(((size_t)b * PP + p) * KK + k) * CC + c0 + cc];
    }
    __syncthreads();
    for (int o = tid; o < 4096; o += 256) {
        int q = o >> 6, cc = o & 63;
        float acc = Fl[q][cc];
        #pragma unroll 8
        for (int p = 0; p < 64; p++) acc += w1[q][p] * Fl[p][cc];
        g_h16[(((size_t)b * PP + q) * KK + k) * CC + c0 + cc] = __float2half(fmaxf(acc, 0.f));
    }
}

__global__ void k_gemm_v(const float* __restrict__ A, const float* __restrict__ Bw,
                         float* __restrict__ C, int M, int N, int K,
                         const float* __restrict__ bias) {
    __shared__ float As[16][68];
    __shared__ float Bs[16][68];
    int m0 = blockIdx.y * 64, n0 = blockIdx.x * 64, tid = threadIdx.x;
    int tx = tid & 15, ty = tid >> 4;
    float acc[4][4] = {};
    for (int k0 = 0; k0 < K; k0 += 16) {
        for (int idx = tid; idx < 1024; idx += 256) {
            int i = idx >> 4, kk = idx & 15;
            int m = m0 + i;
            As[kk][i] = (m < M) ? A[(size_t)m * K + k0 + kk] : 0.f;
        }
        for (int idx = tid; idx < 1024; idx += 256) {
            int j = idx >> 4, kk = idx & 15;
            Bs[kk][j] = Bw[(size_t)(n0 + j) * K + k0 + kk];
        }
        __syncthreads();
        #pragma unroll
        for (int kk = 0; kk < 16; kk++) {
            float a[4], bv[4];
            #pragma unroll
            for (int i = 0; i < 4; i++) a[i] = As[kk][ty * 4 + i];
            #pragma unroll
            for (int j = 0; j < 4; j++) bv[j] = Bs[kk][tx * 4 + j];
            #pragma unroll
            for (int i = 0; i < 4; i++)
                #pragma unroll
                for (int j = 0; j < 4; j++) acc[i][j] += a[i] * bv[j];
        }
        __syncthreads();
    }
    #pragma unroll
    for (int i = 0; i < 4; i++) {
        int m = m0 + ty * 4 + i;
        if (m >= M) continue;
        #pragma unroll
        for (int j = 0; j < 4; j++)
            C[(size_t)m * N + n0 + tx * 4 + j] = acc[i][j] + bias[n0 + tx * 4 + j];
    }
}

__global__ void k_fuse(const float* __restrict__ fw, const float* __restrict__ fb) {
    int bk = blockIdx.x, c = threadIdx.x;
    int b = bk / KK, k = bk % KK;
    float acc = fb[0];
    #pragma unroll 8
    for (int p = 0; p < PP; p++)
        acc += fw[p] * __half2float(g_Fl216[(((size_t)b * PP + p) * KK + k) * CC + c]);
    g_Fg[(size_t)bk * CC + c] = acc;
}

__global__ void k_attn() {
    int bp = blockIdx.x, b = bp >> 6, p = bp & 63;
    int ph = p >> 3, pw = p & 7, tid = threadIdx.x;
    __shared__ float ks[KK][DD];
    __shared__ float vs[KK][DD];
    for (int idx = tid; idx < KK * DD; idx += 256)
        ((float*)ks)[idx] = g_key[(size_t)bp * KK * DD + idx];
    for (int idx = tid; idx < KK * DD; idx += 256)
        ((float*)vs)[idx] = g_value[(size_t)b * KK * DD + idx];
    __syncthreads();
    int warp = tid >> 5, lane = tid & 31;
    for (int n = warp; n < NN; n += 8) {
        int h = ph * 8 + (n >> 3), w = pw * 8 + (n & 7);
        const float* qrow = &g_query[((size_t)b * HW + h * WW + w) * DD];
        float qr[8];
        #pragma unroll
        for (int i = 0; i < 8; i++) qr[i] = qrow[i * 32 + lane];
        float acc[KK];
        #pragma unroll
        for (int k = 0; k < KK; k++) acc[k] = 0.f;
        #pragma unroll
        for (int i = 0; i < 8; i++) {
            float qd = qr[i];
            #pragma unroll
            for (int k = 0; k < KK; k++) acc[k] += qd * ks[k][i * 32 + lane];
        }
        #pragma unroll
        for (int k = 0; k < KK; k++)
            #pragma unroll
            for (int off = 16; off > 0; off >>= 1)
                acc[k] += __shfl_xor_sync(0xFFFFFFFFu, acc[k], off);
        float mx = -1e30f;
        #pragma unroll
        for (int k = 0; k < KK; k++) mx = fmaxf(mx, acc[k]);
        float sum = 0.f;
        #pragma unroll
        for (int k = 0; k < KK; k++) { acc[k] = __expf(acc[k] - mx); sum += acc[k]; }
        float inv = 1.f / sum;
        #pragma unroll
        for (int k = 0; k < KK; k++) acc[k] *= inv;
        size_t ob = ((size_t)b * HW + h * WW + w) * DD;
        #pragma unroll
        for (int i = 0; i < 8; i++) {
            int d = i * 32 + lane;
            float o = 0.f;
            #pragma unroll
            for (int k = 0; k < KK; k++) o += acc[k] * vs[k][d];
            g_Fs16[ob + d] = __float2half(o);
        }
    }
}

// ---------------- 1-term fp16 wmma GEMM ----------------
#define GSTAGE_B 12544
template <int MODE>
__global__ __launch_bounds__(512)
void k_gemm_mma(const h16* __restrict__ Ag, const h16* __restrict__ Wt,
                int K, int N,
                float* __restrict__ Cf, h16* __restrict__ C16,
                const float* __restrict__ bias,
                const float* __restrict__ bng, const float* __restrict__ bnb,
                const float* __restrict__ resid) {
    extern __shared__ char smem[];
    int n0 = blockIdx.x * 128, m0 = blockIdx.y * 256;
    int tid = threadIdx.x, lane = tid & 31, warp = tid >> 5;
    int warpM = warp >> 1, warpN = warp & 1;
    int iters = K >> 4;

    wmma::fragment<wmma::accumulator, 16, 16, 16, float> acc[2][4];
    #pragma unroll
    for (int mt = 0; mt < 2; mt++)
        #pragma unroll
        for (int nj = 0; nj < 4; nj++) wmma::fill_fragment(acc[mt][nj], 0.f);

    auto issue = [&](int it) {
        int k0 = it << 4;
        char* base = smem + (it & 1) * GSTAGE_B;
        h16* As = (h16*)base;
        h16* Ws = (h16*)(base + 8192);
        {
            int flat = tid * 8;
            int r = flat >> 4, c8 = flat & 15;
            cpa16(As + flat, Ag + (size_t)(m0 + r) * K + k0 + c8);
        }
        if (tid < 256) {
            int flat = tid * 8;
            int kk = flat >> 7, n8 = flat & 127;
            cpa16(Ws + kk * 136 + n8, Wt + (size_t)(k0 + kk) * N + n0 + n8);
        }
        cpa_commit();
    };

    issue(0);
    for (int it = 0; it < iters; it++) {
        cpa_wait<0>();
        __syncthreads();
        if (it + 1 < iters) issue(it + 1);
        char* base = smem + (it & 1) * GSTAGE_B;
        h16* As = (h16*)base;
        h16* Ws = (h16*)(base + 8192);
        #pragma unroll
        for (int mt = 0; mt < 2; mt++) {
            int t = warpM * 2 + mt;
            wmma::fragment<wmma::matrix_a, 16, 16, 16, h16, wmma::row_major> af;
            wmma::load_matrix_sync(af, As + t * 256, 16);
            #pragma unroll
            for (int nj = 0; nj < 4; nj++) {
                wmma::fragment<wmma::matrix_b, 16, 16, 16, h16, wmma::row_major> bf;
                wmma::load_matrix_sync(bf, Ws + warpN * 64 + nj * 16, 136);
                wmma::mma_sync(acc[mt][nj], af, bf, acc[mt][nj]);
            }
        }
        __syncthreads();
    }

    float* buf = (float*)smem + warp * 320;
    #pragma unroll
    for (int mt = 0; mt < 2; mt++) {
        int t = warpM * 2 + mt;
        #pragma unroll
        for (int nj = 0; nj < 4; nj++) {
            wmma::store_matrix_sync(buf, acc[mt][nj], 20, wmma::mem_row_major);
            __syncwarp();
            #pragma unroll
            for (int l = 0; l < 8; l++) {
                int e = l * 32 + lane;
                int r = e >> 4, c = e & 15;
                int gm = m0 + t * 16 + r;
                int gn = n0 + warpN * 64 + nj * 16 + c;
                float v = buf[r * 20 + c];
                size_t o = (size_t)gm * N + gn;
                if (MODE == 0) {
                    C16[o] = __float2half(v);
                } else if (MODE == 1) {
                    Cf[o] = v + bias[gn];
                } else {
                    float s = bng[gn] * rsqrtf(1.f + EPS);
                    v = resid[o] + fmaxf(v * s + bnb[gn], 0.f);
                    C16[((size_t)(gn >> 4) * BHW + gm) * 16 + (gn & 15)] = __float2half(v);
                }
            }
            __syncwarp();
        }
    }
}

// ---------------- occ-2 bulk conv: 128px(2 rows) x 128oc, 256 thr, 2-stage ----------------
#define SW_OFF 8448
#define CSTG 47616
#define CONVB_SMEM (2 * CSTG + 64)
__global__ __launch_bounds__(256, 2)
void k_conv_bulk(const h16* __restrict__ inb, int csteps, int cstride, int coff,
                 const h16* __restrict__ wb,
                 const float* __restrict__ bng, const float* __restrict__ bnb,
                 float* __restrict__ out_f, h16* __restrict__ ob,
                 const float* __restrict__ pin, float* __restrict__ praw) {
    extern __shared__ char dsm[];
    char* aptr = (char*)(((size_t)dsm + 127) & ~(size_t)127);
    unsigned int abase = (unsigned int)__cvta_generic_to_shared(aptr);
    unsigned int mbs = abase + 2 * CSTG;

    int tid = threadIdx.x, lane = tid & 31, warp = tid >> 5;
    int warpM = warp >> 1, warpN = warp & 1;
    int b = blockIdx.x >> 5, h0 = (blockIdx.x & 31) << 1;
    int nt = blockIdx.y;
    int oc0 = nt << 7;

    if (tid < 2) mbar_init(mbs + tid * 8, 1);
    // zero-once halos: 2 buffers x 4 rows
    if (tid < 8) {
        int r = tid & 3, bufi = tid >> 2;
        char* rowp = aptr + bufi * CSTG + r * 2112;
        int grow = h0 + r - 1;
        if (grow < 0 || grow >= HH) {
            for (int i = 0; i < 132; i++) ((float4*)rowp)[i] = make_float4(0, 0, 0, 0);
        } else {
            ((float4*)rowp)[0] = make_float4(0, 0, 0, 0);
            ((float4*)rowp)[1] = make_float4(0, 0, 0, 0);
            ((float4*)(rowp + 2080))[0] = make_float4(0, 0, 0, 0);
            ((float4*)(rowp + 2080))[1] = make_float4(0, 0, 0, 0);
        }
    }
    __syncthreads();

    int nvalid = 0;
    for (int r = 0; r < 4; r++) { int g = h0 + r - 1; if (g >= 0 && g < HH) nvalid++; }
    unsigned int txb = 39168u + (unsigned int)nvalid * 2048u;

    auto issue = [&](int s) {
        int bi = s & 1;
        unsigned int base = abase + bi * CSTG;
        unsigned int mb = mbs + bi * 8;
        mbar_expect(mb, txb);
        bulk_cp(base + SW_OFF, wb + (size_t)(nt * cstride + coff + s) * 19584, 39168, mb);
        for (int r = 0; r < 4; r++) {
            int grow = h0 + r - 1;
            if (grow < 0 || grow >= HH) continue;
            size_t so = ((size_t)(s * BATCH + b) * HH + grow) * WW * 16;
            bulk_cp(base + r * 2112 + 32, inb + so, 2048, mb);
        }
    };

    if (tid == 0) {
        issue(0);
        if (csteps > 1) issue(1);
    }
    int ph[2] = {0, 0};

    wmma::fragment<wmma::accumulator, 16, 16, 16, float> acc[2][4];
    #pragma unroll
    for (int mt = 0; mt < 2; mt++)
        #pragma unroll
        for (int nj = 0; nj < 4; nj++) wmma::fill_fragment(acc[mt][nj], 0.f);

    for (int s = 0; s < csteps; s++) {
        int bi = s & 1;
        mbar_wait(mbs + bi * 8, ph[bi]); ph[bi] ^= 1;
        char* base = aptr + bi * CSTG;
        h16* As = (h16*)base;
        h16* Ws = (h16*)(base + SW_OFF);

        #pragma unroll
        for (int tap = 0; tap < 9; tap++) {
            int ky = tap / 3, kx = tap % 3;
            wmma::fragment<wmma::matrix_a, 16, 16, 16, h16, wmma::row_major> af[2];
            #pragma unroll
            for (int mt = 0; mt < 2; mt++) {
                int t = warpM * 2 + mt;
                int row_l = t >> 2, px0 = (t & 3) * 16;
                wmma::load_matrix_sync(af[mt], As + ((row_l + ky) * 66 + px0 + kx) * 16, 16);
            }
            #pragma unroll
            for (int nj = 0; nj < 4; nj++) {
                wmma::fragment<wmma::matrix_b, 16, 16, 16, h16, wmma::row_major> bf;
                wmma::load_matrix_sync(bf, Ws + tap * 2176 + warpN * 64 + nj * 16, 136);
                #pragma unroll
                for (int mt = 0; mt < 2; mt++)
                    wmma::mma_sync(acc[mt][nj], af[mt], bf, acc[mt][nj]);
            }
        }
        __syncthreads();
        if (tid == 0 && s + 2 < csteps) issue(s + 2);
    }

    float* buf = (float*)aptr + warp * 320;
    #pragma unroll
    for (int mt = 0; mt < 2; mt++) {
        int t = warpM * 2 + mt;
        int row_l = t >> 2, px0 = (t & 3) * 16;
        int grow = h0 + row_l;
        #pragma unroll
        for (int nj = 0; nj < 4; nj++) {
            wmma::store_matrix_sync(buf, acc[mt][nj], 20, wmma::mem_row_major);
            __syncwarp();
            #pragma unroll
            for (int l = 0; l < 8; l++) {
                int e = l * 32 + lane;
                int r = e >> 4, c = e & 15;
                int gn = oc0 + warpN * 64 + nj * 16 + c;
                int pix = (b * HH + grow) * WW + px0 + r;
                float v = buf[r * 20 + c];
                if (praw) {
                    praw[(size_t)pix * CC + gn] = v;
                } else {
                    if (pin) v += pin[(size_t)pix * CC + gn];
                    float sc = bng[gn] * rsqrtf(1.f + EPS);
                    v = fmaxf(v * sc + bnb[gn], 0.f);
                    if (out_f) out_f[(size_t)pix * CC + gn] = v;
                    else ob[((size_t)(gn >> 4) * BHW + pix) * 16 + (gn & 15)] = __float2half(v);
                }
            }
            __syncwarp();
        }
    }
}

// ---------------- classifier ----------------
__global__ void k_classifier(const float* __restrict__ drop_w, float* __restrict__ out) {
    __shared__ float Xs[32][65];
    __shared__ float Ws[KK][33];
    int tid = threadIdx.x;
    int row0 = blockIdx.x * 64;
    int b = row0 >> 12, hw0 = row0 & 4095;
    float acc[5] = {0.f, 0.f, 0.f, 0.f, 0.f};
    for (int c0 = 0; c0 < CC; c0 += 32) {
        for (int idx = tid; idx < 2048; idx += 256) {
            int r = idx >> 5, cc = idx & 31;
            Xs[cc][r] = g_x3[(size_t)(row0 + r) * CC + c0 + cc];
        }
        for (int idx = tid; idx < KK * 32; idx += 256) {
            int k = idx >> 5, cc = idx & 31;
            Ws[k][cc] = drop_w[(size_t)k * CC + c0 + cc];
        }
        __syncthreads();
        #pragma unroll
        for (int si = 0; si < 5; si++) {
            int o = tid + si * 256;
            if (o < KK * 64) {
                int k = o >> 6, r = o & 63;
                float a = acc[si];
                #pragma unroll 8
                for (int cc = 0; cc < 32; cc++) a += Ws[k][cc] * Xs[cc][r];
                acc[si] = a;
            }
        }
        __syncthreads();
    }
    #pragma unroll
    for (int si = 0; si < 5; si++) {
        int o = tid + si * 256;
        if (o < KK * 64) {
            int k = o >> 6, r = o & 63;
            out[((size_t)b * KK + k) * HW + hw0 + r] = acc[si];
        }
    }
}

// ---------------- launch (multi-stream graph) ----------------
#define GSA(p, s) cudaGetSymbolAddress((void**)&p, s)
extern "C" void kernel_launch(void* const* d_in, const int* in_sizes, int n_in,
                              void* d_out, int out_size) {
    const float* M_1   = (const float*)d_in[0];
    const float* F     = (const float*)d_in[1];
    const float* I     = (const float*)d_in[2];
    const float* R     = (const float*)d_in[3];
    const float* lg_w1 = (const float*)d_in[4];
    const float* lg_w2 = (const float*)d_in[5];
    const float* fuse_w= (const float*)d_in[6];
    const float* fuse_b= (const float*)d_in[7];
    const float* q_w   = (const float*)d_in[8];
    const float* q_b   = (const float*)d_in[9];
    const float* k_w   = (const float*)d_in[10];
    const float* k_b   = (const float*)d_in[11];
    const float* v_w   = (const float*)d_in[12];
    const float* v_b   = (const float*)d_in[13];
    const float* c1_w  = (const float*)d_in[14];
    const float* bn1_g = (const float*)d_in[15];
    const float* bn1_b = (const float*)d_in[16];
    const float* c2_w  = (const float*)d_in[17];
    const float* bn2_g = (const float*)d_in[18];
    const float* bn2_b = (const float*)d_in[19];
    const float* c3_w  = (const float*)d_in[20];
    const float* bn3_g = (const float*)d_in[21];
    const float* bn3_b = (const float*)d_in[22];
    const float* drop_w= (const float*)d_in[23];
    float* out = (float*)d_out;

    float *p_Fnhwc, *p_Fg, *p_q, *p_k, *p_v, *p_x3, *p_x3p;
    h16 *p_F16, *p_h16, *p_Fl216, *p_Fs16, *p_Fo1b, *p_catb, *p_w2b, *p_w3b;
    h16 *p_qw, *p_kw, *p_lgw, *p_c1;
    GSA(p_Fnhwc, g_Fnhwc); GSA(p_Fg, g_Fg);
    GSA(p_q, g_query); GSA(p_k, g_key); GSA(p_v, g_value);
    GSA(p_x3, g_x3); GSA(p_x3p, g_x3p);
    GSA(p_F16, g_F16); GSA(p_h16, g_h16); GSA(p_Fl216, g_Fl216); GSA(p_Fs16, g_Fs16);
    GSA(p_Fo1b, g_Fo1b); GSA(p_catb, g_catb);
    GSA(p_w2b, g_w2b); GSA(p_w3b, g_w3b);
    GSA(p_qw, g_qw16); GSA(p_kw, g_kw16); GSA(p_lgw, g_lgw16); GSA(p_c1, g_c116);

    static bool init = false;
    static cudaStream_t s1, s2;
    static cudaEvent_t eFork, eTf, eWt, eW2, eQ, eFu, eV, eC3a;
    if (!init) {
        cudaStreamCreateWithFlags(&s1, cudaStreamNonBlocking);
        cudaStreamCreateWithFlags(&s2, cudaStreamNonBlocking);
        cudaEventCreateWithFlags(&eFork, cudaEventDisableTiming);
        cudaEventCreateWithFlags(&eTf,   cudaEventDisableTiming);
        cudaEventCreateWithFlags(&eWt,   cudaEventDisableTiming);
        cudaEventCreateWithFlags(&eW2,   cudaEventDisableTiming);
        cudaEventCreateWithFlags(&eQ,    cudaEventDisableTiming);
        cudaEventCreateWithFlags(&eFu,   cudaEventDisableTiming);
        cudaEventCreateWithFlags(&eV,    cudaEventDisableTiming);
        cudaEventCreateWithFlags(&eC3a,  cudaEventDisableTiming);
        cudaFuncSetAttribute(k_conv_bulk, cudaFuncAttributeMaxDynamicSharedMemorySize, CONVB_SMEM);
        cudaFuncSetAttribute(k_gemm_mma<0>, cudaFuncAttributeMaxDynamicSharedMemorySize, 2 * GSTAGE_B);
        cudaFuncSetAttribute(k_gemm_mma<1>, cudaFuncAttributeMaxDynamicSharedMemorySize, 2 * GSTAGE_B);
        cudaFuncSetAttribute(k_gemm_mma<2>, cudaFuncAttributeMaxDynamicSharedMemorySize, 2 * GSTAGE_B);
        init = true;
    }
    const int GEMM_SMEM = 2 * GSTAGE_B;
    dim3 blk32(32, 8);

    cudaEventRecord(eFork, 0);
    cudaStreamWaitEvent(s1, eFork, 0);
    cudaStreamWaitEvent(s2, eFork, 0);
    // s1: preps, then conv3a over M1 chunks
    k_wt16x<<<dim3(1024, 4), 256, 0, s1>>>(q_w, p_qw, k_w, p_kw, lg_w2, p_lgw, c1_w, p_c1);
    cudaEventRecord(eWt, s1);
    k_wprep<<<(4 * 32 * 19584 + 255) / 256, 256, 0, s1>>>(c2_w, p_w2b, 512, 32);
    cudaEventRecord(eW2, s1);
    k_transpose_m1<<<dim3(HW / 32, 2048 / 32, BATCH), blk32, 0, s1>>>(M_1, p_catb);
    k_wprep<<<(int)(((size_t)4 * 160 * 19584 + 255) / 256), 256, 0, s1>>>(c3_w, p_w3b, 2560, 160);
    k_conv_bulk<<<dim3(BATCH * 32, 4), 256, CONVB_SMEM, s1>>>(
        p_catb + (size_t)32 * BHW * 16, 128, 160, 32, p_w3b,
        nullptr, nullptr, nullptr, nullptr, nullptr, p_x3p);
    cudaEventRecord(eC3a, s1);

    // main chain
    k_transpose_f<<<dim3(HW / 32, CC / 32, BATCH), blk32>>>(F, p_Fnhwc, p_F16);
    cudaEventRecord(eTf, 0);
    k_patch_fl<<<BATCH * PP, 256>>>(I, R);
    k_lg1<<<dim3(CC / 64, BATCH * KK), 256>>>(lg_w1);

    cudaStreamWaitEvent(s2, eTf, 0);
    cudaStreamWaitEvent(s2, eWt, 0);
    k_gemm_mma<1><<<dim3(2, 64), 512, GEMM_SMEM, s2>>>(
        p_F16, p_qw, 512, 256, p_q, nullptr, q_b, nullptr, nullptr, nullptr);
    cudaEventRecord(eQ, s2);

    cudaStreamWaitEvent(0, eWt, 0);
    k_gemm_mma<0><<<dim3(4, 19), 512, GEMM_SMEM>>>(
        p_h16, p_lgw, 512, 512, nullptr, p_Fl216, nullptr, nullptr, nullptr, nullptr);
    k_fuse<<<BATCH * KK, CC>>>(fuse_w, fuse_b);
    cudaEventRecord(eFu, 0);
    cudaStreamWaitEvent(s2, eFu, 0);
    k_gemm_v<<<dim3(DD / 64, 2), 256, 0, s2>>>(p_Fg, v_w, p_v, BATCH * KK, DD, CC, v_b);
    cudaEventRecord(eV, s2);

    k_gemm_mma<1><<<dim3(2, 19), 512, GEMM_SMEM>>>(
        p_Fl216, p_kw, 512, 256, p_k, nullptr, k_b, nullptr, nullptr, nullptr);

    cudaStreamWaitEvent(0, eQ, 0);
    cudaStreamWaitEvent(0, eV, 0);
    k_attn<<<BATCH * PP, 256>>>();

    k_gemm_mma<2><<<dim3(4, 64), 512, GEMM_SMEM>>>(
        p_Fs16, p_c1, 256, 512, nullptr, p_Fo1b, nullptr, bn1_g, bn1_b, p_Fnhwc);

    cudaStreamWaitEvent(0, eW2, 0);
    k_conv_bulk<<<dim3(BATCH * 32, 4), 256, CONVB_SMEM>>>(
        p_Fo1b, 32, 32, 0, p_w2b, bn2_g, bn2_b, nullptr, p_catb, nullptr, nullptr);

    cudaStreamWaitEvent(0, eC3a, 0);
    k_conv_bulk<<<dim3(BATCH * 32, 4), 256, CONVB_SMEM>>>(
        p_catb, 32, 160, 0, p_w3b, bn3_g, bn3_b, p_x3, nullptr, p_x3p, nullptr);

    k_classifier<<<(BATCH * HW) / 64, 256>>>(drop_w, out);
}